// round 6
// baseline (speedup 1.0000x reference)
#include <cuda_runtime.h>
#include <cstddef>
#include <cstdint>

#define NB 128  // batch

// ---------------- output layout (tuple concat, fp32) ----------------
static const size_t O_OUT   = 0;
static const size_t O_PENUL = 1280;
static const size_t O_L1B   = 1049856;
static const size_t O_L1R   = 5244160;
static const size_t O_L2B   = 9438464;
static const size_t O_L2R   = 17827072;
static const size_t O_L3B   = 26215680;
static const size_t O_L3R   = 28312832;
static const size_t O_L4B   = 30409984;
static const size_t O_L4R   = 34604288;
static const size_t O_L5B   = 38798592;
static const size_t O_L5R   = 39847168;

// ---------------- scratch ----------------
__device__ float g_convB[16777216];
__device__ float g_convR[16777216];
__device__ float g_x[16777216];
__device__ float g_poolB[4194304];
__device__ float g_poolR[4194304];
__device__ float g_bw[4571136];
__device__ float g_mean[1024];
__device__ float g_rstd[1024];

static const size_t BW1 = 0;
static const size_t BW2 = 147456;
static const size_t BW3 = 442368;
static const size_t BW4 = 1032192;
static const size_t BW5 = 2211840;

// ---------------- weight sign kernel ----------------
__global__ void wsign_k(const float* __restrict__ w, float* __restrict__ bw, int K) {
    int oc = blockIdx.x;
    int tid = threadIdx.x;
    const float* wp = w + (size_t)oc * K;
    double s = 0.0;
    for (int i = tid; i < K; i += 256) s += (double)wp[i];
    __shared__ double sh[256];
    sh[tid] = s; __syncthreads();
    for (int st = 128; st > 0; st >>= 1) {
        if (tid < st) sh[tid] += sh[tid + st];
        __syncthreads();
    }
    float m = (float)(sh[0] / (double)K);
    float* bp = bw + (size_t)oc * K;
    for (int i = tid; i < K; i += 256) {
        float d = wp[i] - m;
        bp[i] = (d > 0.f) ? 1.f : ((d < 0.f) ? -1.f : 0.f);
    }
}

// ---------------- FFMA direct conv (conv0 only, Cin=3) ----------------
template<int CIN, int HH, bool SIGN_IN>
__global__ void __launch_bounds__(256) conv3x3_k(const float* __restrict__ in,
                                                 const float* __restrict__ w,
                                                 float* __restrict__ out) {
    const int TILES = HH / 8;
    int tile = blockIdx.x;
    int ty0 = (tile / TILES) * 8;
    int tx0 = (tile % TILES) * 8;
    int oc0 = blockIdx.y * 64;
    int n   = blockIdx.z;
    int Cout = gridDim.y * 64;
    int tid = threadIdx.x;
    int pos_t = tid & 15;
    int oc_t  = tid >> 4;

    __shared__ float As[9][64];
    __shared__ float Bs[10][10];

    float acc[4][4];
#pragma unroll
    for (int j = 0; j < 4; j++)
#pragma unroll
        for (int i = 0; i < 4; i++) acc[j][i] = 0.f;

    const float* inN = in + (size_t)n * CIN * HH * HH;

    for (int cin = 0; cin < CIN; cin++) {
        for (int idx = tid; idx < 576; idx += 256) {
            int oc = idx / 9, tap = idx % 9;
            As[tap][oc] = w[(((size_t)(oc0 + oc)) * CIN + cin) * 9 + tap];
        }
        if (tid < 100) {
            int r = tid / 10, c = tid % 10;
            int gy = ty0 + r - 1, gx = tx0 + c - 1;
            float v = 0.f;
            if (gy >= 0 && gy < HH && gx >= 0 && gx < HH)
                v = inN[(size_t)cin * HH * HH + gy * HH + gx];
            if (SIGN_IN) v = (v > 0.f) ? 1.f : ((v < 0.f) ? -1.f : 0.f);
            Bs[r][c] = v;
        }
        __syncthreads();
#pragma unroll
        for (int tap = 0; tap < 9; tap++) {
            int dy = tap / 3, dx = tap % 3;
            float4 wv = *(const float4*)&As[tap][oc_t * 4];
#pragma unroll
            for (int j = 0; j < 4; j++) {
                int p = pos_t + 16 * j;
                float bv = Bs[(p >> 3) + dy][(p & 7) + dx];
                acc[j][0] += bv * wv.x;
                acc[j][1] += bv * wv.y;
                acc[j][2] += bv * wv.z;
                acc[j][3] += bv * wv.w;
            }
        }
        __syncthreads();
    }

#pragma unroll
    for (int j = 0; j < 4; j++) {
        int p = pos_t + 16 * j;
        int oy = ty0 + (p >> 3), ox = tx0 + (p & 7);
#pragma unroll
        for (int i = 0; i < 4; i++) {
            int oc = oc0 + oc_t * 4 + i;
            out[(((size_t)n * Cout + oc) * HH + oy) * HH + ox] = acc[j][i];
        }
    }
}

// ---------------- bf16 pack/convert helpers ----------------
__device__ __forceinline__ uint32_t bf16pack(float evenk, float oddk) {
    uint32_t r;
    asm("cvt.rn.bf16x2.f32 %0, %1, %2;" : "=r"(r) : "f"(oddk), "f"(evenk));
    return r;
}
__device__ __forceinline__ float bf16lo_f(uint32_t p) { return __uint_as_float(p << 16); }
__device__ __forceinline__ float bf16hi_f(uint32_t p) { return __uint_as_float(p & 0xFFFF0000u); }

__device__ __forceinline__ void mma_bf16(float* d, const uint32_t* a, const uint32_t* b) {
    asm volatile(
        "mma.sync.aligned.m16n8k16.row.col.f32.bf16.bf16.f32 "
        "{%0,%1,%2,%3}, {%4,%5,%6,%7}, {%8,%9}, {%0,%1,%2,%3};\n"
        : "+f"(d[0]), "+f"(d[1]), "+f"(d[2]), "+f"(d[3])
        : "r"(a[0]), "r"(a[1]), "r"(a[2]), "r"(a[3]),
          "r"(b[0]), "r"(b[1]));
}

// ---------------- implicit-GEMM conv via bf16 MMA, v2 (fixed staging) ----------------
// Block: 256 threads, 8 warps. Tile M=128 (oc) x N=128 (positions).
// Warp w: m-rows (w&3)*32, n-cols (w>>2)*64.
// Shared memory holds tiles in FRAGMENT order:
//   A: word = m_tile*132 + lane*4 + reg   (reg = a0..a3)
//   B: word = n_tile*68  + lane*2 + reg   (reg = b0..b1)
// Fragment layout (m16n8k16, lane = gid*4+tig):
//   a0 = (row gid,   k 2tig..2tig+1)    a1 = (row gid+8, k 2tig..)
//   a2 = (row gid,   k 8+2tig..)        a3 = (row gid+8, k 8+2tig..)
//   b0 = (col gid,   k 2tig..)          b1 = (col gid,   k 8+2tig..)
// Staging thread (am,akh)/(bc,bkh) writes word:
//   A: m_tile*132 + (am&7)*16 + j*4 + akh*2 + ((am>>3)&1)
//   B: n_tile*68  + (bc&7)*8  + i*2 + bkh
// Double-buffered, software-pipelined, 1 __syncthreads per chunk.
// POOL=true: 2x2 maxpool fused into epilogue (partners are thread-local).
template<int CIN, int H, bool SIGN_IN, bool SPLIT, bool POOL>
__global__ void __launch_bounds__(256, 1) convmma_k(const float* __restrict__ in,
                                                    const float* __restrict__ w,
                                                    float* __restrict__ out,
                                                    int Cout) {
    constexpr int Wd = H;
    constexpr int HW = H * H;
    constexpr int K  = CIN * 9;
    constexpr int NCH = K / 16;
    constexpr int LGHW = (HW == 1024) ? 10 : (HW == 256) ? 8 : 6;
    constexpr int LGW  = (H == 32) ? 5 : (H == 16) ? 4 : 3;
    constexpr int NS = SPLIT ? 2 : 1;

    __shared__ __align__(16) uint32_t As[2][NS][8 * 132];
    __shared__ __align__(16) uint32_t Bs[2][NS][16 * 68];

    int tid  = threadIdx.x;
    int lane = tid & 31;
    int warp = tid >> 5;
    int gid  = lane >> 2;
    int tig  = lane & 3;

    int col0 = blockIdx.x * 128;
    int oc0  = blockIdx.y * 128;

    // ---- staging thread mapping ----
    int am  = tid & 127;          // oc row
    int akh = tid >> 7;           // k half (0/1) within 16-chunk
    const float* wA = w + (size_t)(oc0 + am) * K + akh * 8;
    int aw_base = (am >> 4) * 132 + (am & 7) * 16 + akh * 2 + ((am >> 3) & 1);

    int bc  = tid & 127;          // column
    int bkh = tid >> 7;
    int gcol = col0 + bc;
    int bn   = gcol >> LGHW;
    int bpos = gcol & (HW - 1);
    int by   = bpos >> LGW;
    int bx   = bpos & (Wd - 1);
    const float* inN = in + (size_t)bn * CIN * HW;
    int bw_base = (bc >> 3) * 68 + (bc & 7) * 8 + bkh;

    // incremental cin/tap for the 8 consecutive k rows bkh*8+i
    int cin8[8], tap8[8];
#pragma unroll
    for (int i = 0; i < 8; i++) {
        int r = bkh * 8 + i;
        cin8[i] = r / 9;
        tap8[i] = r % 9;
    }

    float acc[2][8][4];
#pragma unroll
    for (int mt = 0; mt < 2; mt++)
#pragma unroll
        for (int nt = 0; nt < 8; nt++)
#pragma unroll
            for (int r = 0; r < 4; r++) acc[mt][nt][r] = 0.f;

    float av[8], bv[8];

    auto load_chunk = [&](int c) {
        const float* p = wA + c * 16;
        float4 v0 = *(const float4*)(p);
        float4 v1 = *(const float4*)(p + 4);
        av[0] = v0.x; av[1] = v0.y; av[2] = v0.z; av[3] = v0.w;
        av[4] = v1.x; av[5] = v1.y; av[6] = v1.z; av[7] = v1.w;
#pragma unroll
        for (int i = 0; i < 8; i++) {
            int tap = tap8[i];
            int yy = by + tap / 3 - 1;
            int xx = bx + tap % 3 - 1;
            float v = 0.f;
            if (yy >= 0 && yy < H && xx >= 0 && xx < Wd)
                v = inN[cin8[i] * HW + yy * Wd + xx];
            if (SIGN_IN) v = (v > 0.f) ? 1.f : ((v < 0.f) ? -1.f : 0.f);
            bv[i] = v;
            tap8[i] += 7;
            cin8[i] += 1;
            if (tap8[i] >= 9) { tap8[i] -= 9; cin8[i] += 1; }
        }
    };

    auto sts_chunk = [&](int b) {
#pragma unroll
        for (int j = 0; j < 4; j++) {
            uint32_t h = bf16pack(av[2 * j], av[2 * j + 1]);
            As[b][0][aw_base + j * 4] = h;
            if (SPLIT)
                As[b][1][aw_base + j * 4] =
                    bf16pack(av[2 * j] - bf16lo_f(h), av[2 * j + 1] - bf16hi_f(h));
        }
#pragma unroll
        for (int i = 0; i < 4; i++) {
            uint32_t h = bf16pack(bv[2 * i], bv[2 * i + 1]);
            Bs[b][0][bw_base + i * 2] = h;
            if (SPLIT)
                Bs[b][1][bw_base + i * 2] =
                    bf16pack(bv[2 * i] - bf16lo_f(h), bv[2 * i + 1] - bf16hi_f(h));
        }
    };

    int mtile0 = (warp & 3) * 2;
    int ntb    = (warp >> 2) * 8;

    // prologue
    load_chunk(0);
    sts_chunk(0);
    __syncthreads();

    for (int c = 0; c < NCH; c++) {
        int cur = c & 1;
        bool more = (c + 1 < NCH);
        if (more) load_chunk(c + 1);

        uint4 afv[NS][2];
        uint2 bfv[NS][8];
#pragma unroll
        for (int s = 0; s < NS; s++) {
#pragma unroll
            for (int mt = 0; mt < 2; mt++)
                afv[s][mt] = *(const uint4*)&As[cur][s][(mtile0 + mt) * 132 + lane * 4];
#pragma unroll
            for (int nt = 0; nt < 8; nt++)
                bfv[s][nt] = *(const uint2*)&Bs[cur][s][(ntb + nt) * 68 + lane * 2];
        }
#pragma unroll
        for (int mt = 0; mt < 2; mt++)
#pragma unroll
            for (int nt = 0; nt < 8; nt++) {
                if (SPLIT) {
                    mma_bf16(acc[mt][nt], (const uint32_t*)&afv[1][mt], (const uint32_t*)&bfv[0][nt]);
                    mma_bf16(acc[mt][nt], (const uint32_t*)&afv[0][mt], (const uint32_t*)&bfv[1][nt]);
                }
                mma_bf16(acc[mt][nt], (const uint32_t*)&afv[0][mt], (const uint32_t*)&bfv[0][nt]);
            }

        if (more) sts_chunk(cur ^ 1);
        __syncthreads();
    }

    // ---- epilogue ----
    int ncol0 = col0 + (warp >> 2) * 64;
    if (!POOL) {
#pragma unroll
        for (int mt = 0; mt < 2; mt++) {
#pragma unroll
            for (int nt = 0; nt < 8; nt++) {
                int cc = ncol0 + nt * 8 + 2 * tig;
                int n_ = cc >> LGHW;
                int pp = cc & (HW - 1);
#pragma unroll
                for (int h = 0; h < 2; h++) {
                    int m = oc0 + (warp & 3) * 32 + mt * 16 + gid + 8 * h;
                    float2 v = make_float2(acc[mt][nt][2 * h], acc[mt][nt][2 * h + 1]);
                    *(float2*)&out[((size_t)n_ * Cout + m) * HW + pp] = v;
                }
            }
        }
    } else {
        constexpr int PST = H / 8;        // nt stride to the y+1 partner row
        constexpr int HO = H / 2;
#pragma unroll
        for (int mt = 0; mt < 2; mt++) {
#pragma unroll
            for (int nt = 0; nt < 8; nt++) {
                if (((nt / PST) & 1) != 0) continue;   // only even pool rows
                int np = nt + PST;
                int cc = ncol0 + nt * 8 + 2 * tig;
                int n_ = cc >> LGHW;
                int pos = cc & (HW - 1);
                int oy = (pos >> LGW) >> 1;
                int ox = (pos & (Wd - 1)) >> 1;
#pragma unroll
                for (int h = 0; h < 2; h++) {
                    int m = oc0 + (warp & 3) * 32 + mt * 16 + gid + 8 * h;
                    float v = fmaxf(fmaxf(acc[mt][nt][2 * h], acc[mt][nt][2 * h + 1]),
                                    fmaxf(acc[mt][np][2 * h], acc[mt][np][2 * h + 1]));
                    out[((size_t)n_ * Cout + m) * (HO * HO) + oy * HO + ox] = v;
                }
            }
        }
    }
}

// ---------------- BN stats ----------------
__global__ void bnstats_k(const float* __restrict__ x, int C, int HW,
                          float* __restrict__ mean, float* __restrict__ rstd) {
    int c = blockIdx.x;
    int tid = threadIdx.x;
    double s1 = 0.0, s2 = 0.0;
    for (int n = 0; n < NB; n++) {
        const float* xp = x + ((size_t)n * C + c) * HW;
        for (int p = tid; p < HW; p += 256) {
            float v = xp[p];
            s1 += (double)v;
            s2 += (double)v * (double)v;
        }
    }
    __shared__ double sh1[256], sh2[256];
    sh1[tid] = s1; sh2[tid] = s2; __syncthreads();
    for (int st = 128; st > 0; st >>= 1) {
        if (tid < st) { sh1[tid] += sh1[tid + st]; sh2[tid] += sh2[tid + st]; }
        __syncthreads();
    }
    if (tid == 0) {
        double M = (double)NB * HW;
        double m = sh1[0] / M;
        double var = sh2[0] / M - m * m;
        mean[c] = (float)m;
        rstd[c] = (float)(1.0 / sqrt(var + 1e-5));
    }
}

// ---------------- BN apply + hardtanh ----------------
__global__ void bnht_k(const float* __restrict__ x, float* __restrict__ y,
                       const float* __restrict__ mean, const float* __restrict__ rstd,
                       const float* __restrict__ g, const float* __restrict__ bb,
                       int lgHW, int Cmask) {
    size_t i = (size_t)blockIdx.x * 256 + threadIdx.x;
    int c = (int)((i >> lgHW) & (size_t)Cmask);
    float v = (x[i] - mean[c]) * rstd[c] * g[c] + bb[c];
    y[i] = fminf(1.f, fmaxf(-1.f, v));
}

// ---------------- copy ----------------
__global__ void copy_k(const float* __restrict__ src, float* __restrict__ dst) {
    size_t i = (size_t)blockIdx.x * 256 + threadIdx.x;
    dst[i] = src[i];
}

// ---------------- FC ----------------
__global__ void fc_k(const float* __restrict__ p, const float* __restrict__ w,
                     const float* __restrict__ b, float* __restrict__ out) {
    int n = blockIdx.x;
    int tid = threadIdx.x;
    float acc[10];
#pragma unroll
    for (int j = 0; j < 10; j++) acc[j] = 0.f;
    const float* pn = p + (size_t)n * 8192;
    for (int k = tid; k < 8192; k += 256) {
        float pv = pn[k];
#pragma unroll
        for (int j = 0; j < 10; j++) acc[j] += pv * w[(size_t)j * 8192 + k];
    }
    __shared__ float sh[256];
    for (int j = 0; j < 10; j++) {
        sh[tid] = acc[j]; __syncthreads();
        for (int st = 128; st > 0; st >>= 1) {
            if (tid < st) sh[tid] += sh[tid + st];
            __syncthreads();
        }
        if (tid == 0) out[n * 10 + j] = sh[0] + b[j];
        __syncthreads();
    }
}

// ---------------- host launch ----------------
extern "C" void kernel_launch(void* const* d_in, const int* in_sizes, int n_in,
                              void* d_out, int out_size) {
    (void)in_sizes; (void)n_in; (void)out_size;
    const float* x   = (const float*)d_in[0];
    const float* w0  = (const float*)d_in[1];
    const float* w1  = (const float*)d_in[2];
    const float* w2  = (const float*)d_in[3];
    const float* w3  = (const float*)d_in[4];
    const float* w4  = (const float*)d_in[5];
    const float* w5  = (const float*)d_in[6];
    const float* fcw = (const float*)d_in[7];
    const float* fcb = (const float*)d_in[8];
    const float* G[6], *B[6];
    for (int i = 0; i < 6; i++) { G[i] = (const float*)d_in[9 + 2*i]; B[i] = (const float*)d_in[10 + 2*i]; }
    float* out = (float*)d_out;

    float *convB, *convR, *xb, *poolB, *poolR, *bw, *mean, *rstd;
    cudaGetSymbolAddress((void**)&convB, g_convB);
    cudaGetSymbolAddress((void**)&convR, g_convR);
    cudaGetSymbolAddress((void**)&xb,    g_x);
    cudaGetSymbolAddress((void**)&poolB, g_poolB);
    cudaGetSymbolAddress((void**)&poolR, g_poolR);
    cudaGetSymbolAddress((void**)&bw,    g_bw);
    cudaGetSymbolAddress((void**)&mean,  g_mean);
    cudaGetSymbolAddress((void**)&rstd,  g_rstd);

    // launch order: index 5 = convmma L1 binary (profiled by ncu -s 5 -c 1)
    conv3x3_k<3, 32, false><<<dim3(16, 2, NB), 256>>>(x, w0, convB);
    wsign_k<<<128, 256>>>(w1, bw + BW1, 128 * 9);
    bnstats_k<<<128, 256>>>(convB, 128, 1024, mean, rstd);
    bnht_k<<<(NB * 128 * 1024) / 256, 256>>>(convB, xb, mean, rstd, G[0], B[0], 10, 127);
    wsign_k<<<256, 256>>>(w2, bw + BW2, 128 * 9);

    // Layer 1: 128->128 @32, fused pool -> 16
    convmma_k<128, 32, true,  false, true><<<dim3(1024, 1), 256>>>(xb, bw + BW1, poolB, 128);
    convmma_k<128, 32, false, true,  true><<<dim3(1024, 1), 256>>>(xb, w1,       poolR, 128);
    wsign_k<<<256, 256>>>(w3, bw + BW3, 256 * 9);
    wsign_k<<<512, 256>>>(w4, bw + BW4, 256 * 9);
    wsign_k<<<512, 256>>>(w5, bw + BW5, 512 * 9);
    bnstats_k<<<128, 256>>>(poolB, 128, 256, mean, rstd);
    bnht_k<<<(NB * 128 * 256) / 256, 256>>>(poolB, out + O_L1B, mean, rstd, G[1], B[1], 8, 127);
    bnstats_k<<<128, 256>>>(poolR, 128, 256, mean + 512, rstd + 512);
    bnht_k<<<(NB * 128 * 256) / 256, 256>>>(poolR, out + O_L1R, mean + 512, rstd + 512, G[1], B[1], 8, 127);

    // Layer 2: 128->256 @16, no pool
    convmma_k<128, 16, true,  false, false><<<dim3(256, 2), 256>>>(out + O_L1B, bw + BW2, convB, 256);
    convmma_k<128, 16, false, true,  false><<<dim3(256, 2), 256>>>(out + O_L1R, w2,       convR, 256);
    bnstats_k<<<256, 256>>>(convB, 256, 256, mean, rstd);
    bnht_k<<<(NB * 256 * 256) / 256, 256>>>(convB, out + O_L2B, mean, rstd, G[2], B[2], 8, 255);
    bnstats_k<<<256, 256>>>(convR, 256, 256, mean + 512, rstd + 512);
    bnht_k<<<(NB * 256 * 256) / 256, 256>>>(convR, out + O_L2R, mean + 512, rstd + 512, G[2], B[2], 8, 255);

    // Layer 3: 256->256 @16, fused pool -> 8
    convmma_k<256, 16, true,  false, true><<<dim3(256, 2), 256>>>(out + O_L2B, bw + BW3, poolB, 256);
    convmma_k<256, 16, false, true,  true><<<dim3(256, 2), 256>>>(out + O_L2R, w3,       poolR, 256);
    bnstats_k<<<256, 256>>>(poolB, 256, 64, mean, rstd);
    bnht_k<<<(NB * 256 * 64) / 256, 256>>>(poolB, out + O_L3B, mean, rstd, G[3], B[3], 6, 255);
    bnstats_k<<<256, 256>>>(poolR, 256, 64, mean + 512, rstd + 512);
    bnht_k<<<(NB * 256 * 64) / 256, 256>>>(poolR, out + O_L3R, mean + 512, rstd + 512, G[3], B[3], 6, 255);

    // Layer 4: 256->512 @8, no pool
    convmma_k<256, 8, true,  false, false><<<dim3(64, 4), 256>>>(out + O_L3B, bw + BW4, convB, 512);
    convmma_k<256, 8, false, true,  false><<<dim3(64, 4), 256>>>(out + O_L3R, w4,       convR, 512);
    bnstats_k<<<512, 256>>>(convB, 512, 64, mean, rstd);
    bnht_k<<<(NB * 512 * 64) / 256, 256>>>(convB, out + O_L4B, mean, rstd, G[4], B[4], 6, 511);
    bnstats_k<<<512, 256>>>(convR, 512, 64, mean + 512, rstd + 512);
    bnht_k<<<(NB * 512 * 64) / 256, 256>>>(convR, out + O_L4R, mean + 512, rstd + 512, G[4], B[4], 6, 511);

    // Layer 5: 512->512 @8, fused pool -> 4
    convmma_k<512, 8, true,  false, true><<<dim3(64, 4), 256>>>(out + O_L4B, bw + BW5, poolB, 512);
    convmma_k<512, 8, false, true,  true><<<dim3(64, 4), 256>>>(out + O_L4R, w5,       poolR, 512);
    bnstats_k<<<512, 256>>>(poolB, 512, 16, mean, rstd);
    bnht_k<<<(NB * 512 * 16) / 256, 256>>>(poolB, out + O_L5B, mean, rstd, G[5], B[5], 4, 511);
    bnstats_k<<<512, 256>>>(poolR, 512, 16, mean + 512, rstd + 512);
    bnht_k<<<(NB * 512 * 16) / 256, 256>>>(poolR, out + O_L5R, mean + 512, rstd + 512, G[5], B[5], 4, 511);

    // penul + FC
    copy_k<<<(NB * 8192) / 256, 256>>>(out + O_L5B, out + O_PENUL);
    fc_k<<<NB, 256>>>(out + O_PENUL, fcw, fcb, out + O_OUT);
}

// round 8
// speedup vs baseline: 1.0733x; 1.0733x over previous
#include <cuda_runtime.h>
#include <cstddef>
#include <cstdint>

#define NB 128  // batch

// ---------------- output layout (tuple concat, fp32) ----------------
static const size_t O_OUT   = 0;
static const size_t O_PENUL = 1280;
static const size_t O_L1B   = 1049856;
static const size_t O_L1R   = 5244160;
static const size_t O_L2B   = 9438464;
static const size_t O_L2R   = 17827072;
static const size_t O_L3B   = 26215680;
static const size_t O_L3R   = 28312832;
static const size_t O_L4B   = 30409984;
static const size_t O_L4R   = 34604288;
static const size_t O_L5B   = 38798592;
static const size_t O_L5R   = 39847168;

// ---------------- scratch ----------------
__device__ float g_convB[16777216];
__device__ float g_convR[16777216];
__device__ float g_x[16777216];
__device__ float g_poolB[4194304];
__device__ float g_poolR[4194304];
__device__ float g_bw[4571136];
__device__ float g_mean[1024];
__device__ float g_rstd[1024];

static const size_t BW1 = 0;
static const size_t BW2 = 147456;
static const size_t BW3 = 442368;
static const size_t BW4 = 1032192;
static const size_t BW5 = 2211840;

// ---------------- weight sign kernel ----------------
__global__ void wsign_k(const float* __restrict__ w, float* __restrict__ bw, int K) {
    int oc = blockIdx.x;
    int tid = threadIdx.x;
    const float* wp = w + (size_t)oc * K;
    double s = 0.0;
    for (int i = tid; i < K; i += 256) s += (double)wp[i];
    __shared__ double sh[256];
    sh[tid] = s; __syncthreads();
    for (int st = 128; st > 0; st >>= 1) {
        if (tid < st) sh[tid] += sh[tid + st];
        __syncthreads();
    }
    float m = (float)(sh[0] / (double)K);
    float* bp = bw + (size_t)oc * K;
    for (int i = tid; i < K; i += 256) {
        float d = wp[i] - m;
        bp[i] = (d > 0.f) ? 1.f : ((d < 0.f) ? -1.f : 0.f);
    }
}

// ---------------- FFMA direct conv (conv0 only, Cin=3) ----------------
template<int CIN, int HH, bool SIGN_IN>
__global__ void __launch_bounds__(256) conv3x3_k(const float* __restrict__ in,
                                                 const float* __restrict__ w,
                                                 float* __restrict__ out) {
    const int TILES = HH / 8;
    int tile = blockIdx.x;
    int ty0 = (tile / TILES) * 8;
    int tx0 = (tile % TILES) * 8;
    int oc0 = blockIdx.y * 64;
    int n   = blockIdx.z;
    int Cout = gridDim.y * 64;
    int tid = threadIdx.x;
    int pos_t = tid & 15;
    int oc_t  = tid >> 4;

    __shared__ float As[9][64];
    __shared__ float Bs[10][10];

    float acc[4][4];
#pragma unroll
    for (int j = 0; j < 4; j++)
#pragma unroll
        for (int i = 0; i < 4; i++) acc[j][i] = 0.f;

    const float* inN = in + (size_t)n * CIN * HH * HH;

    for (int cin = 0; cin < CIN; cin++) {
        for (int idx = tid; idx < 576; idx += 256) {
            int oc = idx / 9, tap = idx % 9;
            As[tap][oc] = w[(((size_t)(oc0 + oc)) * CIN + cin) * 9 + tap];
        }
        if (tid < 100) {
            int r = tid / 10, c = tid % 10;
            int gy = ty0 + r - 1, gx = tx0 + c - 1;
            float v = 0.f;
            if (gy >= 0 && gy < HH && gx >= 0 && gx < HH)
                v = inN[(size_t)cin * HH * HH + gy * HH + gx];
            if (SIGN_IN) v = (v > 0.f) ? 1.f : ((v < 0.f) ? -1.f : 0.f);
            Bs[r][c] = v;
        }
        __syncthreads();
#pragma unroll
        for (int tap = 0; tap < 9; tap++) {
            int dy = tap / 3, dx = tap % 3;
            float4 wv = *(const float4*)&As[tap][oc_t * 4];
#pragma unroll
            for (int j = 0; j < 4; j++) {
                int p = pos_t + 16 * j;
                float bv = Bs[(p >> 3) + dy][(p & 7) + dx];
                acc[j][0] += bv * wv.x;
                acc[j][1] += bv * wv.y;
                acc[j][2] += bv * wv.z;
                acc[j][3] += bv * wv.w;
            }
        }
        __syncthreads();
    }

#pragma unroll
    for (int j = 0; j < 4; j++) {
        int p = pos_t + 16 * j;
        int oy = ty0 + (p >> 3), ox = tx0 + (p & 7);
#pragma unroll
        for (int i = 0; i < 4; i++) {
            int oc = oc0 + oc_t * 4 + i;
            out[(((size_t)n * Cout + oc) * HH + oy) * HH + ox] = acc[j][i];
        }
    }
}

// ---------------- bf16 pack/convert helpers ----------------
__device__ __forceinline__ uint32_t bf16pack(float evenk, float oddk) {
    uint32_t r;
    asm("cvt.rn.bf16x2.f32 %0, %1, %2;" : "=r"(r) : "f"(oddk), "f"(evenk));
    return r;
}
__device__ __forceinline__ float bf16lo_f(uint32_t p) { return __uint_as_float(p << 16); }
__device__ __forceinline__ float bf16hi_f(uint32_t p) { return __uint_as_float(p & 0xFFFF0000u); }

__device__ __forceinline__ void mma_bf16(float* d, const uint32_t* a, const uint32_t* b) {
    asm volatile(
        "mma.sync.aligned.m16n8k16.row.col.f32.bf16.bf16.f32 "
        "{%0,%1,%2,%3}, {%4,%5,%6,%7}, {%8,%9}, {%0,%1,%2,%3};\n"
        : "+f"(d[0]), "+f"(d[1]), "+f"(d[2]), "+f"(d[3])
        : "r"(a[0]), "r"(a[1]), "r"(a[2]), "r"(a[3]),
          "r"(b[0]), "r"(b[1]));
}

// ---------------- implicit-GEMM conv via bf16 MMA (round-4 shape + pipeline + fused pool) ----------------
// Block: 128 threads, 4 warps. Tile M=128 (oc) x N=64 (positions); warp tile 32x64.
// K = CIN*9, chunked by 16. Double-buffered smem, 1 __syncthreads per chunk,
// next chunk's LDGs issued before the LDS+MMA block.
// SPLIT: bf16x2 hi/lo decomposition (3 MMAs) for the real branch.
// POOL:  fused 2x2 maxpool epilogue (partner row = nt + H/8, partner col in-register).
template<int CIN, int H, bool SIGN_IN, bool SPLIT, bool POOL>
__global__ void __launch_bounds__(128) convmma_k(const float* __restrict__ in,
                                                 const float* __restrict__ w,
                                                 float* __restrict__ out,
                                                 int Cout) {
    constexpr int Wd = H;
    constexpr int HW = H * H;
    constexpr int K  = CIN * 9;
    constexpr int NCH = K / 16;
    constexpr int LGHW = (HW == 1024) ? 10 : (HW == 256) ? 8 : 6;
    constexpr int LGW  = (H == 32) ? 5 : (H == 16) ? 4 : 3;
    constexpr int NS = SPLIT ? 2 : 1;

    __shared__ uint32_t As[2][NS][8][136];  // [buf][plane][kpair][m]
    __shared__ uint32_t Bs[2][NS][8][72];   // [buf][plane][kpair][n]

    int tid  = threadIdx.x;
    int lane = tid & 31;
    int warp = tid >> 5;
    int gid  = lane >> 2;   // 0..7
    int tig  = lane & 3;    // 0..3

    int col0 = blockIdx.x * 64;
    int oc0  = blockIdx.y * 128;

    // B-gather mapping: thread handles column bc, k-rows br2*8 + i (i=0..7)
    int bc  = tid & 63;
    int br2 = tid >> 6;     // 0 or 1
    int gcol = col0 + bc;
    int n   = gcol >> LGHW;
    int pos = gcol & (HW - 1);
    int y   = pos >> LGW;
    int x   = pos & (Wd - 1);
    const float* inN = in + (size_t)n * CIN * HW;

    int cin8[8], tap8[8];
#pragma unroll
    for (int i = 0; i < 8; i++) {
        int r = br2 * 8 + i;
        cin8[i] = r / 9;
        tap8[i] = r % 9;
    }

    float acc[2][8][4];
#pragma unroll
    for (int mt = 0; mt < 2; mt++)
#pragma unroll
        for (int nt = 0; nt < 8; nt++)
#pragma unroll
            for (int r = 0; r < 4; r++) acc[mt][nt][r] = 0.f;

    const float* wA = w + (size_t)(oc0 + tid) * K;

    float4 va[4];
    float  bv[8];

    // issue LDGs + gather for chunk c into registers
    auto load_chunk = [&](int c) {
        const float* p = wA + c * 16;
        va[0] = *(const float4*)(p);
        va[1] = *(const float4*)(p + 4);
        va[2] = *(const float4*)(p + 8);
        va[3] = *(const float4*)(p + 12);
#pragma unroll
        for (int i = 0; i < 8; i++) {
            int tap = tap8[i];
            int yy = y + tap / 3 - 1;
            int xx = x + tap % 3 - 1;
            float v = 0.f;
            if (yy >= 0 && yy < H && xx >= 0 && xx < Wd)
                v = inN[cin8[i] * HW + yy * Wd + xx];
            if (SIGN_IN) v = (v > 0.f) ? 1.f : ((v < 0.f) ? -1.f : 0.f);
            bv[i] = v;
            tap8[i] += 7;
            cin8[i] += 1;
            if (tap8[i] >= 9) { tap8[i] -= 9; cin8[i] += 1; }
        }
    };

    // pack registers -> shared buffer b
    auto sts_chunk = [&](int b) {
#pragma unroll
        for (int j = 0; j < 4; j++) {
            uint32_t h0 = bf16pack(va[j].x, va[j].y);
            uint32_t h1 = bf16pack(va[j].z, va[j].w);
            As[b][0][2 * j + 0][tid] = h0;
            As[b][0][2 * j + 1][tid] = h1;
            if (SPLIT) {
                As[b][1][2 * j + 0][tid] = bf16pack(va[j].x - bf16lo_f(h0), va[j].y - bf16hi_f(h0));
                As[b][1][2 * j + 1][tid] = bf16pack(va[j].z - bf16lo_f(h1), va[j].w - bf16hi_f(h1));
            }
        }
#pragma unroll
        for (int t = 0; t < 4; t++) {
            uint32_t h = bf16pack(bv[2 * t], bv[2 * t + 1]);
            Bs[b][0][br2 * 4 + t][bc] = h;
            if (SPLIT)
                Bs[b][1][br2 * 4 + t][bc] =
                    bf16pack(bv[2 * t] - bf16lo_f(h), bv[2 * t + 1] - bf16hi_f(h));
        }
    };

    // prologue
    load_chunk(0);
    sts_chunk(0);
    __syncthreads();

    for (int c = 0; c < NCH; c++) {
        int cur = c & 1;
        bool more = (c + 1 < NCH);
        if (more) load_chunk(c + 1);   // LDGs in flight during LDS+MMA

        uint32_t af[NS][2][4], bf[NS][8][2];
#pragma unroll
        for (int s = 0; s < NS; s++) {
#pragma unroll
            for (int mt = 0; mt < 2; mt++) {
                int m0 = warp * 32 + mt * 16 + gid;
                af[s][mt][0] = As[cur][s][tig][m0];
                af[s][mt][1] = As[cur][s][tig][m0 + 8];
                af[s][mt][2] = As[cur][s][tig + 4][m0];
                af[s][mt][3] = As[cur][s][tig + 4][m0 + 8];
            }
#pragma unroll
            for (int nt = 0; nt < 8; nt++) {
                bf[s][nt][0] = Bs[cur][s][tig][nt * 8 + gid];
                bf[s][nt][1] = Bs[cur][s][tig + 4][nt * 8 + gid];
            }
        }
#pragma unroll
        for (int mt = 0; mt < 2; mt++)
#pragma unroll
            for (int nt = 0; nt < 8; nt++) {
                if (SPLIT) {
                    mma_bf16(acc[mt][nt], af[1][mt], bf[0][nt]);
                    mma_bf16(acc[mt][nt], af[0][mt], bf[1][nt]);
                }
                mma_bf16(acc[mt][nt], af[0][mt], bf[0][nt]);
            }

        if (more) sts_chunk(cur ^ 1);
        __syncthreads();
    }

    // ---- epilogue ----
    if (!POOL) {
#pragma unroll
        for (int mt = 0; mt < 2; mt++) {
#pragma unroll
            for (int nt = 0; nt < 8; nt++) {
                int cc = col0 + nt * 8 + 2 * tig;
                int n_ = cc >> LGHW;
                int pp = cc & (HW - 1);
#pragma unroll
                for (int h = 0; h < 2; h++) {
                    int m = oc0 + warp * 32 + mt * 16 + gid + 8 * h;
                    float2 v = make_float2(acc[mt][nt][2 * h], acc[mt][nt][2 * h + 1]);
                    *(float2*)&out[((size_t)n_ * Cout + m) * HW + pp] = v;
                }
            }
        }
    } else {
        constexpr int PST = H / 8;   // nt stride to the y+1 partner row
        constexpr int HO = H / 2;
#pragma unroll
        for (int mt = 0; mt < 2; mt++) {
#pragma unroll
            for (int nt = 0; nt < 8; nt++) {
                if (((nt / PST) & 1) != 0) continue;   // only even pool rows
                int np = nt + PST;
                int cc = col0 + nt * 8 + 2 * tig;
                int n_ = cc >> LGHW;
                int pos_ = cc & (HW - 1);
                int oy = (pos_ >> LGW) >> 1;
                int ox = (pos_ & (Wd - 1)) >> 1;
#pragma unroll
                for (int h = 0; h < 2; h++) {
                    int m = oc0 + warp * 32 + mt * 16 + gid + 8 * h;
                    float v = fmaxf(fmaxf(acc[mt][nt][2 * h], acc[mt][nt][2 * h + 1]),
                                    fmaxf(acc[mt][np][2 * h], acc[mt][np][2 * h + 1]));
                    out[((size_t)n_ * Cout + m) * (HO * HO) + oy * HO + ox] = v;
                }
            }
        }
    }
}

// ---------------- BN stats ----------------
__global__ void bnstats_k(const float* __restrict__ x, int C, int HW,
                          float* __restrict__ mean, float* __restrict__ rstd) {
    int c = blockIdx.x;
    int tid = threadIdx.x;
    double s1 = 0.0, s2 = 0.0;
    for (int n = 0; n < NB; n++) {
        const float* xp = x + ((size_t)n * C + c) * HW;
        for (int p = tid; p < HW; p += 256) {
            float v = xp[p];
            s1 += (double)v;
            s2 += (double)v * (double)v;
        }
    }
    __shared__ double sh1[256], sh2[256];
    sh1[tid] = s1; sh2[tid] = s2; __syncthreads();
    for (int st = 128; st > 0; st >>= 1) {
        if (tid < st) { sh1[tid] += sh1[tid + st]; sh2[tid] += sh2[tid + st]; }
        __syncthreads();
    }
    if (tid == 0) {
        double M = (double)NB * HW;
        double m = sh1[0] / M;
        double var = sh2[0] / M - m * m;
        mean[c] = (float)m;
        rstd[c] = (float)(1.0 / sqrt(var + 1e-5));
    }
}

// ---------------- BN apply + hardtanh ----------------
__global__ void bnht_k(const float* __restrict__ x, float* __restrict__ y,
                       const float* __restrict__ mean, const float* __restrict__ rstd,
                       const float* __restrict__ g, const float* __restrict__ bb,
                       int lgHW, int Cmask) {
    size_t i = (size_t)blockIdx.x * 256 + threadIdx.x;
    int c = (int)((i >> lgHW) & (size_t)Cmask);
    float v = (x[i] - mean[c]) * rstd[c] * g[c] + bb[c];
    y[i] = fminf(1.f, fmaxf(-1.f, v));
}

// ---------------- copy ----------------
__global__ void copy_k(const float* __restrict__ src, float* __restrict__ dst) {
    size_t i = (size_t)blockIdx.x * 256 + threadIdx.x;
    dst[i] = src[i];
}

// ---------------- FC ----------------
__global__ void fc_k(const float* __restrict__ p, const float* __restrict__ w,
                     const float* __restrict__ b, float* __restrict__ out) {
    int n = blockIdx.x;
    int tid = threadIdx.x;
    float acc[10];
#pragma unroll
    for (int j = 0; j < 10; j++) acc[j] = 0.f;
    const float* pn = p + (size_t)n * 8192;
    for (int k = tid; k < 8192; k += 256) {
        float pv = pn[k];
#pragma unroll
        for (int j = 0; j < 10; j++) acc[j] += pv * w[(size_t)j * 8192 + k];
    }
    __shared__ float sh[256];
    for (int j = 0; j < 10; j++) {
        sh[tid] = acc[j]; __syncthreads();
        for (int st = 128; st > 0; st >>= 1) {
            if (tid < st) sh[tid] += sh[tid + st];
            __syncthreads();
        }
        if (tid == 0) out[n * 10 + j] = sh[0] + b[j];
        __syncthreads();
    }
}

// ---------------- host launch ----------------
extern "C" void kernel_launch(void* const* d_in, const int* in_sizes, int n_in,
                              void* d_out, int out_size) {
    (void)in_sizes; (void)n_in; (void)out_size;
    const float* x   = (const float*)d_in[0];
    const float* w0  = (const float*)d_in[1];
    const float* w1  = (const float*)d_in[2];
    const float* w2  = (const float*)d_in[3];
    const float* w3  = (const float*)d_in[4];
    const float* w4  = (const float*)d_in[5];
    const float* w5  = (const float*)d_in[6];
    const float* fcw = (const float*)d_in[7];
    const float* fcb = (const float*)d_in[8];
    const float* G[6], *B[6];
    for (int i = 0; i < 6; i++) { G[i] = (const float*)d_in[9 + 2*i]; B[i] = (const float*)d_in[10 + 2*i]; }
    float* out = (float*)d_out;

    float *convB, *convR, *xb, *poolB, *poolR, *bw, *mean, *rstd;
    cudaGetSymbolAddress((void**)&convB, g_convB);
    cudaGetSymbolAddress((void**)&convR, g_convR);
    cudaGetSymbolAddress((void**)&xb,    g_x);
    cudaGetSymbolAddress((void**)&poolB, g_poolB);
    cudaGetSymbolAddress((void**)&poolR, g_poolR);
    cudaGetSymbolAddress((void**)&bw,    g_bw);
    cudaGetSymbolAddress((void**)&mean,  g_mean);
    cudaGetSymbolAddress((void**)&rstd,  g_rstd);

    // launch order: index 5 = convmma L1 binary (profiled by ncu -s 5 -c 1)
    conv3x3_k<3, 32, false><<<dim3(16, 2, NB), 256>>>(x, w0, convB);
    wsign_k<<<128, 256>>>(w1, bw + BW1, 128 * 9);
    bnstats_k<<<128, 256>>>(convB, 128, 1024, mean, rstd);
    bnht_k<<<(NB * 128 * 1024) / 256, 256>>>(convB, xb, mean, rstd, G[0], B[0], 10, 127);
    wsign_k<<<256, 256>>>(w2, bw + BW2, 128 * 9);

    // Layer 1: 128->128 @32, fused pool -> 16
    convmma_k<128, 32, true,  false, true><<<dim3(2048, 1), 128>>>(xb, bw + BW1, poolB, 128);
    convmma_k<128, 32, false, true,  true><<<dim3(2048, 1), 128>>>(xb, w1,       poolR, 128);
    wsign_k<<<256, 256>>>(w3, bw + BW3, 256 * 9);
    wsign_k<<<512, 256>>>(w4, bw + BW4, 256 * 9);
    wsign_k<<<512, 256>>>(w5, bw + BW5, 512 * 9);
    bnstats_k<<<128, 256>>>(poolB, 128, 256, mean, rstd);
    bnht_k<<<(NB * 128 * 256) / 256, 256>>>(poolB, out + O_L1B, mean, rstd, G[1], B[1], 8, 127);
    bnstats_k<<<128, 256>>>(poolR, 128, 256, mean + 512, rstd + 512);
    bnht_k<<<(NB * 128 * 256) / 256, 256>>>(poolR, out + O_L1R, mean + 512, rstd + 512, G[1], B[1], 8, 127);

    // Layer 2: 128->256 @16, no pool
    convmma_k<128, 16, true,  false, false><<<dim3(512, 2), 128>>>(out + O_L1B, bw + BW2, convB, 256);
    convmma_k<128, 16, false, true,  false><<<dim3(512, 2), 128>>>(out + O_L1R, w2,       convR, 256);
    bnstats_k<<<256, 256>>>(convB, 256, 256, mean, rstd);
    bnht_k<<<(NB * 256 * 256) / 256, 256>>>(convB, out + O_L2B, mean, rstd, G[2], B[2], 8, 255);
    bnstats_k<<<256, 256>>>(convR, 256, 256, mean + 512, rstd + 512);
    bnht_k<<<(NB * 256 * 256) / 256, 256>>>(convR, out + O_L2R, mean + 512, rstd + 512, G[2], B[2], 8, 255);

    // Layer 3: 256->256 @16, fused pool -> 8
    convmma_k<256, 16, true,  false, true><<<dim3(512, 2), 128>>>(out + O_L2B, bw + BW3, poolB, 256);
    convmma_k<256, 16, false, true,  true><<<dim3(512, 2), 128>>>(out + O_L2R, w3,       poolR, 256);
    bnstats_k<<<256, 256>>>(poolB, 256, 64, mean, rstd);
    bnht_k<<<(NB * 256 * 64) / 256, 256>>>(poolB, out + O_L3B, mean, rstd, G[3], B[3], 6, 255);
    bnstats_k<<<256, 256>>>(poolR, 256, 64, mean + 512, rstd + 512);
    bnht_k<<<(NB * 256 * 64) / 256, 256>>>(poolR, out + O_L3R, mean + 512, rstd + 512, G[3], B[3], 6, 255);

    // Layer 4: 256->512 @8, no pool
    convmma_k<256, 8, true,  false, false><<<dim3(128, 4), 128>>>(out + O_L3B, bw + BW4, convB, 512);
    convmma_k<256, 8, false, true,  false><<<dim3(128, 4), 128>>>(out + O_L3R, w4,       convR, 512);
    bnstats_k<<<512, 256>>>(convB, 512, 64, mean, rstd);
    bnht_k<<<(NB * 512 * 64) / 256, 256>>>(convB, out + O_L4B, mean, rstd, G[4], B[4], 6, 511);
    bnstats_k<<<512, 256>>>(convR, 512, 64, mean + 512, rstd + 512);
    bnht_k<<<(NB * 512 * 64) / 256, 256>>>(convR, out + O_L4R, mean + 512, rstd + 512, G[4], B[4], 6, 511);

    // Layer 5: 512->512 @8, fused pool -> 4
    convmma_k<512, 8, true,  false, true><<<dim3(128, 4), 128>>>(out + O_L4B, bw + BW5, poolB, 512);
    convmma_k<512, 8, false, true,  true><<<dim3(128, 4), 128>>>(out + O_L4R, w5,       poolR, 512);
    bnstats_k<<<512, 256>>>(poolB, 512, 16, mean, rstd);
    bnht_k<<<(NB * 512 * 16) / 256, 256>>>(poolB, out + O_L5B, mean, rstd, G[5], B[5], 4, 511);
    bnstats_k<<<512, 256>>>(poolR, 512, 16, mean + 512, rstd + 512);
    bnht_k<<<(NB * 512 * 16) / 256, 256>>>(poolR, out + O_L5R, mean + 512, rstd + 512, G[5], B[5], 4, 511);

    // penul + FC
    copy_k<<<(NB * 8192) / 256, 256>>>(out + O_L5B, out + O_PENUL);
    fc_k<<<NB, 256>>>(out + O_PENUL, fcw, fcb, out + O_OUT);
}

// round 9
// speedup vs baseline: 1.2126x; 1.1298x over previous
#include <cuda_runtime.h>
#include <cstddef>
#include <cstdint>

#define NB 128  // batch

// ---------------- output layout (tuple concat, fp32) ----------------
static const size_t O_OUT   = 0;
static const size_t O_PENUL = 1280;
static const size_t O_L1B   = 1049856;
static const size_t O_L1R   = 5244160;
static const size_t O_L2B   = 9438464;
static const size_t O_L2R   = 17827072;
static const size_t O_L3B   = 26215680;
static const size_t O_L3R   = 28312832;
static const size_t O_L4B   = 30409984;
static const size_t O_L4R   = 34604288;
static const size_t O_L5B   = 38798592;
static const size_t O_L5R   = 39847168;

// ---------------- scratch ----------------
__device__ float    g_convB[16777216];
__device__ float    g_convR[16777216];
__device__ float    g_poolB[4194304];
__device__ float    g_poolR[4194304];
__device__ uint16_t g_pbin[2][16777216];   // channel-last bf16 sign planes (ping-pong)
__device__ uint32_t g_preal[2][16777216];  // channel-last hi|lo bf16 planes (ping-pong)
__device__ uint16_t g_bwb[4571136];        // transposed prepacked binary weights [oc][tap][cin]
__device__ uint32_t g_bwr[4571136];        // transposed prepacked real weights hi|lo
__device__ float    g_mean[1024];
__device__ float    g_rstd[1024];

static const size_t BW1 = 0;         // 128*128*9
static const size_t BW2 = 147456;    // 256*128*9
static const size_t BW3 = 442368;    // 256*256*9
static const size_t BW4 = 1032192;   // 512*256*9
static const size_t BW5 = 2211840;   // 512*512*9

// ---------------- bf16 helpers ----------------
__device__ __forceinline__ uint16_t f2bf(float x) {
    uint16_t r; asm("cvt.rn.bf16.f32 %0, %1;" : "=h"(r) : "f"(x)); return r;
}
__device__ __forceinline__ float bf2f(uint16_t h) {
    return __uint_as_float(((uint32_t)h) << 16);
}
__device__ __forceinline__ uint32_t prmt(uint32_t a, uint32_t b, uint32_t c) {
    uint32_t r; asm("prmt.b32 %0, %1, %2, %3;" : "=r"(r) : "r"(a), "r"(b), "r"(c)); return r;
}

// ---------------- weight prep: binary sign, transposed tap-major, bf16 ----------------
__global__ void wsignT_k(const float* __restrict__ w, uint16_t* __restrict__ bwT, int CIN) {
    int oc = blockIdx.x;
    int tid = threadIdx.x;
    int K = CIN * 9;
    const float* wp = w + (size_t)oc * K;
    double s = 0.0;
    for (int i = tid; i < K; i += 256) s += (double)wp[i];
    __shared__ double sh[256];
    sh[tid] = s; __syncthreads();
    for (int st = 128; st > 0; st >>= 1) {
        if (tid < st) sh[tid] += sh[tid + st];
        __syncthreads();
    }
    float m = (float)(sh[0] / (double)K);
    for (int i = tid; i < K; i += 256) {
        float d = wp[i] - m;
        uint16_t v = (d > 0.f) ? 0x3F80 : ((d < 0.f) ? 0xBF80 : 0);
        int cin = i / 9, tap = i % 9;
        bwT[((size_t)oc * 9 + tap) * CIN + cin] = v;
    }
}

// ---------------- weight prep: real hi/lo bf16, transposed tap-major ----------------
__global__ void wrealT_k(const float* __restrict__ w, uint32_t* __restrict__ wT, int CIN) {
    size_t i = (size_t)blockIdx.x * 256 + threadIdx.x;
    int tap = (int)(i % 9);
    size_t t = i / 9;
    int cin = (int)(t % CIN);
    int oc  = (int)(t / CIN);
    float x = w[i];
    uint16_t hi = f2bf(x);
    float lo = x - bf2f(hi);
    wT[((size_t)oc * 9 + tap) * CIN + cin] = (uint32_t)hi | ((uint32_t)f2bf(lo) << 16);
}

// ---------------- FFMA direct conv (conv0 only, Cin=3) ----------------
template<int CIN, int HH>
__global__ void __launch_bounds__(256) conv3x3_k(const float* __restrict__ in,
                                                 const float* __restrict__ w,
                                                 float* __restrict__ out) {
    const int TILES = HH / 8;
    int tile = blockIdx.x;
    int ty0 = (tile / TILES) * 8;
    int tx0 = (tile % TILES) * 8;
    int oc0 = blockIdx.y * 64;
    int n   = blockIdx.z;
    int Cout = gridDim.y * 64;
    int tid = threadIdx.x;
    int pos_t = tid & 15;
    int oc_t  = tid >> 4;

    __shared__ float As[9][64];
    __shared__ float Bs[10][10];

    float acc[4][4];
#pragma unroll
    for (int j = 0; j < 4; j++)
#pragma unroll
        for (int i = 0; i < 4; i++) acc[j][i] = 0.f;

    const float* inN = in + (size_t)n * CIN * HH * HH;

    for (int cin = 0; cin < CIN; cin++) {
        for (int idx = tid; idx < 576; idx += 256) {
            int oc = idx / 9, tap = idx % 9;
            As[tap][oc] = w[(((size_t)(oc0 + oc)) * CIN + cin) * 9 + tap];
        }
        if (tid < 100) {
            int r = tid / 10, c = tid % 10;
            int gy = ty0 + r - 1, gx = tx0 + c - 1;
            float v = 0.f;
            if (gy >= 0 && gy < HH && gx >= 0 && gx < HH)
                v = inN[(size_t)cin * HH * HH + gy * HH + gx];
            Bs[r][c] = v;
        }
        __syncthreads();
#pragma unroll
        for (int tap = 0; tap < 9; tap++) {
            int dy = tap / 3, dx = tap % 3;
            float4 wv = *(const float4*)&As[tap][oc_t * 4];
#pragma unroll
            for (int j = 0; j < 4; j++) {
                int p = pos_t + 16 * j;
                float bv = Bs[(p >> 3) + dy][(p & 7) + dx];
                acc[j][0] += bv * wv.x;
                acc[j][1] += bv * wv.y;
                acc[j][2] += bv * wv.z;
                acc[j][3] += bv * wv.w;
            }
        }
        __syncthreads();
    }

#pragma unroll
    for (int j = 0; j < 4; j++) {
        int p = pos_t + 16 * j;
        int oy = ty0 + (p >> 3), ox = tx0 + (p & 7);
#pragma unroll
        for (int i = 0; i < 4; i++) {
            int oc = oc0 + oc_t * 4 + i;
            out[(((size_t)n * Cout + oc) * HH + oy) * HH + ox] = acc[j][i];
        }
    }
}

// ---------------- bf16 MMA ----------------
__device__ __forceinline__ void mma_bf16(float* d, const uint32_t* a, const uint32_t* b) {
    asm volatile(
        "mma.sync.aligned.m16n8k16.row.col.f32.bf16.bf16.f32 "
        "{%0,%1,%2,%3}, {%4,%5,%6,%7}, {%8,%9}, {%0,%1,%2,%3};\n"
        : "+f"(d[0]), "+f"(d[1]), "+f"(d[2]), "+f"(d[3])
        : "r"(a[0]), "r"(a[1]), "r"(a[2]), "r"(a[3]),
          "r"(b[0]), "r"(b[1]));
}

// ---------------- implicit-GEMM conv v3: prepacked planes, tap-major K ----------------
// Block: 128 threads, 4 warps. Tile M=128 (oc) x N=64 (positions); warp tile 32x64.
// K order = tap*CIN + cin; chunks of 16 lie within one tap (CIN%16==0).
// A: prepacked transposed weights (binary: u16 bf16; real: u32 hi|lo).
// B: channel-last activation planes [n][h][w][c] (binary: u16 bf16 sign; real: u32 hi|lo).
//    One (predicated) LDG.128 per thread per chunk for binary B; zero per-element math.
// Smem fragment layout identical to the proven round-4/8 scheme.
template<int CIN, int H, bool SPLIT, bool POOL>
__global__ void __launch_bounds__(128) convmma_k(const void* __restrict__ inplane,
                                                 const void* __restrict__ wT,
                                                 float* __restrict__ out,
                                                 int Cout) {
    constexpr int Wd = H;
    constexpr int HW = H * H;
    constexpr int K  = CIN * 9;
    constexpr int NCH = K / 16;
    constexpr int LGHW = (HW == 1024) ? 10 : (HW == 256) ? 8 : 6;
    constexpr int LGW  = (H == 32) ? 5 : (H == 16) ? 4 : 3;
    constexpr int NS = SPLIT ? 2 : 1;

    __shared__ uint32_t As[2][NS][8][136];
    __shared__ uint32_t Bs[2][NS][8][72];

    int tid  = threadIdx.x;
    int lane = tid & 31;
    int warp = tid >> 5;
    int gid  = lane >> 2;
    int tig  = lane & 3;

    int col0 = blockIdx.x * 64;
    int oc0  = blockIdx.y * 128;

    // B mapping: column bc, k-rows bkh*8 + 0..7 (= 8 consecutive cins of one tap)
    int bc  = tid & 63;
    int bkh = tid >> 6;
    int gcol = col0 + bc;
    int n   = gcol >> LGHW;
    int pos = gcol & (HW - 1);
    int y   = pos >> LGW;
    int x   = pos & (Wd - 1);

    const uint16_t* aw16 = (const uint16_t*)wT + (size_t)(oc0 + tid) * K;
    const uint32_t* aw32 = (const uint32_t*)wT + (size_t)(oc0 + tid) * K;
    const uint16_t* bp16 = (const uint16_t*)inplane;
    const uint32_t* bp32 = (const uint32_t*)inplane;

    // tap state
    int cin0 = 0, dy = -1, dx = -1;
    bool valid;
    size_t rowoff;
    {
        int iy = y + dy, ix = x + dx;
        valid = (iy >= 0 && iy < H && ix >= 0 && ix < Wd);
        rowoff = ((size_t)n * HW + (size_t)(iy * Wd + ix)) * CIN;
    }

    float acc[2][8][4];
#pragma unroll
    for (int mt = 0; mt < 2; mt++)
#pragma unroll
        for (int nt = 0; nt < 8; nt++)
#pragma unroll
            for (int r = 0; r < 4; r++) acc[mt][nt][r] = 0.f;

    uint4 va[4], vb[2];
    const uint4 z4 = make_uint4(0, 0, 0, 0);

    auto load_chunk = [&](int c) {
        int k0 = c * 16;
        if (!SPLIT) {
            va[0] = *(const uint4*)(aw16 + k0);
            va[1] = *(const uint4*)(aw16 + k0 + 8);
            vb[0] = valid ? *(const uint4*)(bp16 + rowoff + cin0 + bkh * 8) : z4;
        } else {
            va[0] = *(const uint4*)(aw32 + k0);
            va[1] = *(const uint4*)(aw32 + k0 + 4);
            va[2] = *(const uint4*)(aw32 + k0 + 8);
            va[3] = *(const uint4*)(aw32 + k0 + 12);
            if (valid) {
                vb[0] = *(const uint4*)(bp32 + rowoff + cin0 + bkh * 8);
                vb[1] = *(const uint4*)(bp32 + rowoff + cin0 + bkh * 8 + 4);
            } else { vb[0] = z4; vb[1] = z4; }
        }
        // advance tap state
        cin0 += 16;
        if (cin0 == CIN) {
            cin0 = 0;
            dx++;
            if (dx > 1) { dx = -1; dy++; }
            int iy = y + dy, ix = x + dx;
            valid = (iy >= 0 && iy < H && ix >= 0 && ix < Wd);
            rowoff = ((size_t)n * HW + (size_t)(iy * Wd + ix)) * CIN;
        }
    };

    auto sts_chunk = [&](int b) {
        if (!SPLIT) {
            As[b][0][0][tid] = va[0].x; As[b][0][1][tid] = va[0].y;
            As[b][0][2][tid] = va[0].z; As[b][0][3][tid] = va[0].w;
            As[b][0][4][tid] = va[1].x; As[b][0][5][tid] = va[1].y;
            As[b][0][6][tid] = va[1].z; As[b][0][7][tid] = va[1].w;
            Bs[b][0][bkh * 4 + 0][bc] = vb[0].x;
            Bs[b][0][bkh * 4 + 1][bc] = vb[0].y;
            Bs[b][0][bkh * 4 + 2][bc] = vb[0].z;
            Bs[b][0][bkh * 4 + 3][bc] = vb[0].w;
        } else {
#pragma unroll
            for (int q = 0; q < 4; q++) {
                uint4 v = va[q];
                As[b][0][2 * q + 0][tid] = prmt(v.x, v.y, 0x5410);
                As[b][1][2 * q + 0][tid] = prmt(v.x, v.y, 0x7632);
                As[b][0][2 * q + 1][tid] = prmt(v.z, v.w, 0x5410);
                As[b][1][2 * q + 1][tid] = prmt(v.z, v.w, 0x7632);
            }
            Bs[b][0][bkh * 4 + 0][bc] = prmt(vb[0].x, vb[0].y, 0x5410);
            Bs[b][1][bkh * 4 + 0][bc] = prmt(vb[0].x, vb[0].y, 0x7632);
            Bs[b][0][bkh * 4 + 1][bc] = prmt(vb[0].z, vb[0].w, 0x5410);
            Bs[b][1][bkh * 4 + 1][bc] = prmt(vb[0].z, vb[0].w, 0x7632);
            Bs[b][0][bkh * 4 + 2][bc] = prmt(vb[1].x, vb[1].y, 0x5410);
            Bs[b][1][bkh * 4 + 2][bc] = prmt(vb[1].x, vb[1].y, 0x7632);
            Bs[b][0][bkh * 4 + 3][bc] = prmt(vb[1].z, vb[1].w, 0x5410);
            Bs[b][1][bkh * 4 + 3][bc] = prmt(vb[1].z, vb[1].w, 0x7632);
        }
    };

    // prologue
    load_chunk(0);
    sts_chunk(0);
    __syncthreads();

    for (int c = 0; c < NCH; c++) {
        int cur = c & 1;
        bool more = (c + 1 < NCH);
        if (more) load_chunk(c + 1);

        uint32_t af[NS][2][4], bf[NS][8][2];
#pragma unroll
        for (int s = 0; s < NS; s++) {
#pragma unroll
            for (int mt = 0; mt < 2; mt++) {
                int m0 = warp * 32 + mt * 16 + gid;
                af[s][mt][0] = As[cur][s][tig][m0];
                af[s][mt][1] = As[cur][s][tig][m0 + 8];
                af[s][mt][2] = As[cur][s][tig + 4][m0];
                af[s][mt][3] = As[cur][s][tig + 4][m0 + 8];
            }
#pragma unroll
            for (int nt = 0; nt < 8; nt++) {
                bf[s][nt][0] = Bs[cur][s][tig][nt * 8 + gid];
                bf[s][nt][1] = Bs[cur][s][tig + 4][nt * 8 + gid];
            }
        }
#pragma unroll
        for (int mt = 0; mt < 2; mt++)
#pragma unroll
            for (int nt = 0; nt < 8; nt++) {
                if (SPLIT) {
                    mma_bf16(acc[mt][nt], af[1][mt], bf[0][nt]);
                    mma_bf16(acc[mt][nt], af[0][mt], bf[1][nt]);
                }
                mma_bf16(acc[mt][nt], af[0][mt], bf[0][nt]);
            }

        if (more) sts_chunk(cur ^ 1);
        __syncthreads();
    }

    // ---- epilogue (identical to round 8) ----
    if (!POOL) {
#pragma unroll
        for (int mt = 0; mt < 2; mt++) {
#pragma unroll
            for (int nt = 0; nt < 8; nt++) {
                int cc = col0 + nt * 8 + 2 * tig;
                int n_ = cc >> LGHW;
                int pp = cc & (HW - 1);
#pragma unroll
                for (int h = 0; h < 2; h++) {
                    int m = oc0 + warp * 32 + mt * 16 + gid + 8 * h;
                    float2 v = make_float2(acc[mt][nt][2 * h], acc[mt][nt][2 * h + 1]);
                    *(float2*)&out[((size_t)n_ * Cout + m) * HW + pp] = v;
                }
            }
        }
    } else {
        constexpr int PST = H / 8;
        constexpr int HO = H / 2;
#pragma unroll
        for (int mt = 0; mt < 2; mt++) {
#pragma unroll
            for (int nt = 0; nt < 8; nt++) {
                if (((nt / PST) & 1) != 0) continue;
                int np = nt + PST;
                int cc = col0 + nt * 8 + 2 * tig;
                int n_ = cc >> LGHW;
                int pos_ = cc & (HW - 1);
                int oy = (pos_ >> LGW) >> 1;
                int ox = (pos_ & (Wd - 1)) >> 1;
#pragma unroll
                for (int h = 0; h < 2; h++) {
                    int m = oc0 + warp * 32 + mt * 16 + gid + 8 * h;
                    float v = fmaxf(fmaxf(acc[mt][nt][2 * h], acc[mt][nt][2 * h + 1]),
                                    fmaxf(acc[mt][np][2 * h], acc[mt][np][2 * h + 1]));
                    out[((size_t)n_ * Cout + m) * (HO * HO) + oy * HO + ox] = v;
                }
            }
        }
    }
}

// ---------------- BN stats ----------------
__global__ void bnstats_k(const float* __restrict__ x, int C, int HW,
                          float* __restrict__ mean, float* __restrict__ rstd) {
    int c = blockIdx.x;
    int tid = threadIdx.x;
    double s1 = 0.0, s2 = 0.0;
    for (int n = 0; n < NB; n++) {
        const float* xp = x + ((size_t)n * C + c) * HW;
        for (int p = tid; p < HW; p += 256) {
            float v = xp[p];
            s1 += (double)v;
            s2 += (double)v * (double)v;
        }
    }
    __shared__ double sh1[256], sh2[256];
    sh1[tid] = s1; sh2[tid] = s2; __syncthreads();
    for (int st = 128; st > 0; st >>= 1) {
        if (tid < st) { sh1[tid] += sh1[tid + st]; sh2[tid] += sh2[tid + st]; }
        __syncthreads();
    }
    if (tid == 0) {
        double M = (double)NB * HW;
        double m = sh1[0] / M;
        double var = sh2[0] / M - m * m;
        mean[c] = (float)m;
        rstd[c] = (float)(1.0 / sqrt(var + 1e-5));
    }
}

// ---------------- BN apply + hardtanh + channel-last plane pack ----------------
// Block 256 = 32x8; tile 32c x 32p per n; smem transpose for coalesced plane writes.
// Grid: (HW/32, C/32, NB).
template<bool BIN, bool REALP, bool WF32>
__global__ void bnht_pack_k(const float* __restrict__ x, float* __restrict__ y32,
                            uint16_t* __restrict__ pbin, uint32_t* __restrict__ preal,
                            const float* __restrict__ mean, const float* __restrict__ rstd,
                            const float* __restrict__ g, const float* __restrict__ bb,
                            int C, int HW) {
    __shared__ float ts[32][33];
    int tx = threadIdx.x & 31, ty = threadIdx.x >> 5;
    int p0 = blockIdx.x * 32, c0 = blockIdx.y * 32, n = blockIdx.z;
#pragma unroll
    for (int r = 0; r < 4; r++) {
        int c = c0 + ty + r * 8;
        size_t idx = ((size_t)n * C + c) * HW + p0 + tx;
        float v = x[idx];
        v = (v - mean[c]) * rstd[c] * g[c] + bb[c];
        v = fminf(1.f, fmaxf(-1.f, v));
        if (WF32) y32[idx] = v;
        ts[ty + r * 8][tx] = v;
    }
    __syncthreads();
#pragma unroll
    for (int r = 0; r < 4; r++) {
        int p = p0 + ty + r * 8;
        int c = c0 + tx;
        float v = ts[tx][ty + r * 8];
        size_t a = ((size_t)n * HW + p) * C + c;
        if (BIN)
            pbin[a] = (v > 0.f) ? 0x3F80 : ((v < 0.f) ? 0xBF80 : 0);
        if (REALP) {
            uint16_t hi = f2bf(v);
            float lo = v - bf2f(hi);
            preal[a] = (uint32_t)hi | ((uint32_t)f2bf(lo) << 16);
        }
    }
}

// ---------------- plain BN apply + hardtanh (L5 outputs) ----------------
__global__ void bnht_k(const float* __restrict__ x, float* __restrict__ y,
                       const float* __restrict__ mean, const float* __restrict__ rstd,
                       const float* __restrict__ g, const float* __restrict__ bb,
                       int lgHW, int Cmask) {
    size_t i = (size_t)blockIdx.x * 256 + threadIdx.x;
    int c = (int)((i >> lgHW) & (size_t)Cmask);
    float v = (x[i] - mean[c]) * rstd[c] * g[c] + bb[c];
    y[i] = fminf(1.f, fmaxf(-1.f, v));
}

// ---------------- copy ----------------
__global__ void copy_k(const float* __restrict__ src, float* __restrict__ dst) {
    size_t i = (size_t)blockIdx.x * 256 + threadIdx.x;
    dst[i] = src[i];
}

// ---------------- FC ----------------
__global__ void fc_k(const float* __restrict__ p, const float* __restrict__ w,
                     const float* __restrict__ b, float* __restrict__ out) {
    int n = blockIdx.x;
    int tid = threadIdx.x;
    float acc[10];
#pragma unroll
    for (int j = 0; j < 10; j++) acc[j] = 0.f;
    const float* pn = p + (size_t)n * 8192;
    for (int k = tid; k < 8192; k += 256) {
        float pv = pn[k];
#pragma unroll
        for (int j = 0; j < 10; j++) acc[j] += pv * w[(size_t)j * 8192 + k];
    }
    __shared__ float sh[256];
    for (int j = 0; j < 10; j++) {
        sh[tid] = acc[j]; __syncthreads();
        for (int st = 128; st > 0; st >>= 1) {
            if (tid < st) sh[tid] += sh[tid + st];
            __syncthreads();
        }
        if (tid == 0) out[n * 10 + j] = sh[0] + b[j];
        __syncthreads();
    }
}

// ---------------- host launch ----------------
extern "C" void kernel_launch(void* const* d_in, const int* in_sizes, int n_in,
                              void* d_out, int out_size) {
    (void)in_sizes; (void)n_in; (void)out_size;
    const float* x   = (const float*)d_in[0];
    const float* w0  = (const float*)d_in[1];
    const float* w1  = (const float*)d_in[2];
    const float* w2  = (const float*)d_in[3];
    const float* w3  = (const float*)d_in[4];
    const float* w4  = (const float*)d_in[5];
    const float* w5  = (const float*)d_in[6];
    const float* fcw = (const float*)d_in[7];
    const float* fcb = (const float*)d_in[8];
    const float* G[6], *B[6];
    for (int i = 0; i < 6; i++) { G[i] = (const float*)d_in[9 + 2*i]; B[i] = (const float*)d_in[10 + 2*i]; }
    float* out = (float*)d_out;

    float *convB, *convR, *poolB, *poolR, *mean, *rstd;
    uint16_t *pbin, *bwb;
    uint32_t *preal, *bwr;
    cudaGetSymbolAddress((void**)&convB, g_convB);
    cudaGetSymbolAddress((void**)&convR, g_convR);
    cudaGetSymbolAddress((void**)&poolB, g_poolB);
    cudaGetSymbolAddress((void**)&poolR, g_poolR);
    cudaGetSymbolAddress((void**)&pbin,  g_pbin);
    cudaGetSymbolAddress((void**)&preal, g_preal);
    cudaGetSymbolAddress((void**)&bwb,   g_bwb);
    cudaGetSymbolAddress((void**)&bwr,   g_bwr);
    cudaGetSymbolAddress((void**)&mean,  g_mean);
    cudaGetSymbolAddress((void**)&rstd,  g_rstd);
    uint16_t* pb[2] = { pbin, pbin + 16777216 };
    uint32_t* pr[2] = { preal, preal + 16777216 };

    // launch order: index 5 = convmma L1 binary (profiled by ncu -s 5 -c 1)
    conv3x3_k<3, 32><<<dim3(16, 2, NB), 256>>>(x, w0, convB);                       // 0
    wsignT_k<<<128, 256>>>(w1, bwb + BW1, 128);                                     // 1
    bnstats_k<<<128, 256>>>(convB, 128, 1024, mean, rstd);                          // 2
    wrealT_k<<<576, 256>>>(w1, bwr + BW1, 128);                                     // 3
    bnht_pack_k<true, true, false><<<dim3(32, 4, NB), 256>>>(                       // 4
        convB, nullptr, pb[0], pr[0], mean, rstd, G[0], B[0], 128, 1024);

    // Layer 1: 128->128 @32, fused pool -> 16
    convmma_k<128, 32, false, true><<<dim3(2048, 1), 128>>>(pb[0], bwb + BW1, poolB, 128);  // 5
    convmma_k<128, 32, true,  true><<<dim3(2048, 1), 128>>>(pr[0], bwr + BW1, poolR, 128);
    wsignT_k<<<256, 256>>>(w2, bwb + BW2, 128);
    wrealT_k<<<1152, 256>>>(w2, bwr + BW2, 128);
    wsignT_k<<<256, 256>>>(w3, bwb + BW3, 256);
    wrealT_k<<<2304, 256>>>(w3, bwr + BW3, 256);
    wsignT_k<<<512, 256>>>(w4, bwb + BW4, 256);
    wrealT_k<<<4608, 256>>>(w4, bwr + BW4, 256);
    wsignT_k<<<512, 256>>>(w5, bwb + BW5, 512);
    wrealT_k<<<9216, 256>>>(w5, bwr + BW5, 512);
    bnstats_k<<<128, 256>>>(poolB, 128, 256, mean, rstd);
    bnht_pack_k<true, false, true><<<dim3(8, 4, NB), 256>>>(
        poolB, out + O_L1B, pb[1], nullptr, mean, rstd, G[1], B[1], 128, 256);
    bnstats_k<<<128, 256>>>(poolR, 128, 256, mean + 512, rstd + 512);
    bnht_pack_k<false, true, true><<<dim3(8, 4, NB), 256>>>(
        poolR, out + O_L1R, nullptr, pr[1], mean + 512, rstd + 512, G[1], B[1], 128, 256);

    // Layer 2: 128->256 @16, no pool
    convmma_k<128, 16, false, false><<<dim3(512, 2), 128>>>(pb[1], bwb + BW2, convB, 256);
    convmma_k<128, 16, true,  false><<<dim3(512, 2), 128>>>(pr[1], bwr + BW2, convR, 256);
    bnstats_k<<<256, 256>>>(convB, 256, 256, mean, rstd);
    bnht_pack_k<true, false, true><<<dim3(8, 8, NB), 256>>>(
        convB, out + O_L2B, pb[0], nullptr, mean, rstd, G[2], B[2], 256, 256);
    bnstats_k<<<256, 256>>>(convR, 256, 256, mean + 512, rstd + 512);
    bnht_pack_k<false, true, true><<<dim3(8, 8, NB), 256>>>(
        convR, out + O_L2R, nullptr, pr[0], mean + 512, rstd + 512, G[2], B[2], 256, 256);

    // Layer 3: 256->256 @16, fused pool -> 8
    convmma_k<256, 16, false, true><<<dim3(512, 2), 128>>>(pb[0], bwb + BW3, poolB, 256);
    convmma_k<256, 16, true,  true><<<dim3(512, 2), 128>>>(pr[0], bwr + BW3, poolR, 256);
    bnstats_k<<<256, 256>>>(poolB, 256, 64, mean, rstd);
    bnht_pack_k<true, false, true><<<dim3(2, 8, NB), 256>>>(
        poolB, out + O_L3B, pb[1], nullptr, mean, rstd, G[3], B[3], 256, 64);
    bnstats_k<<<256, 256>>>(poolR, 256, 64, mean + 512, rstd + 512);
    bnht_pack_k<false, true, true><<<dim3(2, 8, NB), 256>>>(
        poolR, out + O_L3R, nullptr, pr[1], mean + 512, rstd + 512, G[3], B[3], 256, 64);

    // Layer 4: 256->512 @8, no pool
    convmma_k<256, 8, false, false><<<dim3(128, 4), 128>>>(pb[1], bwb + BW4, convB, 512);
    convmma_k<256, 8, true,  false><<<dim3(128, 4), 128>>>(pr[1], bwr + BW4, convR, 512);
    bnstats_k<<<512, 256>>>(convB, 512, 64, mean, rstd);
    bnht_pack_k<true, false, true><<<dim3(2, 16, NB), 256>>>(
        convB, out + O_L4B, pb[0], nullptr, mean, rstd, G[4], B[4], 512, 64);
    bnstats_k<<<512, 256>>>(convR, 512, 64, mean + 512, rstd + 512);
    bnht_pack_k<false, true, true><<<dim3(2, 16, NB), 256>>>(
        convR, out + O_L4R, nullptr, pr[0], mean + 512, rstd + 512, G[4], B[4], 512, 64);

    // Layer 5: 512->512 @8, fused pool -> 4
    convmma_k<512, 8, false, true><<<dim3(128, 4), 128>>>(pb[0], bwb + BW5, poolB, 512);
    convmma_k<512, 8, true,  true><<<dim3(128, 4), 128>>>(pr[0], bwr + BW5, poolR, 512);
    bnstats_k<<<512, 256>>>(poolB, 512, 16, mean, rstd);
    bnht_k<<<(NB * 512 * 16) / 256, 256>>>(poolB, out + O_L5B, mean, rstd, G[5], B[5], 4, 511);
    bnstats_k<<<512, 256>>>(poolR, 512, 16, mean + 512, rstd + 512);
    bnht_k<<<(NB * 512 * 16) / 256, 256>>>(poolR, out + O_L5R, mean + 512, rstd + 512, G[5], B[5], 4, 511);

    // penul + FC
    copy_k<<<(NB * 8192) / 256, 256>>>(out + O_L5B, out + O_PENUL);
    fc_k<<<NB, 256>>>(out + O_PENUL, fcw, fcb, out + O_OUT);
}

// round 10
// speedup vs baseline: 1.2255x; 1.0106x over previous
#include <cuda_runtime.h>
#include <cstddef>
#include <cstdint>

#define NB 128  // batch

// ---------------- output layout (tuple concat, fp32) ----------------
static const size_t O_OUT   = 0;
static const size_t O_PENUL = 1280;
static const size_t O_L1B   = 1049856;
static const size_t O_L1R   = 5244160;
static const size_t O_L2B   = 9438464;
static const size_t O_L2R   = 17827072;
static const size_t O_L3B   = 26215680;
static const size_t O_L3R   = 28312832;
static const size_t O_L4B   = 30409984;
static const size_t O_L4R   = 34604288;
static const size_t O_L5B   = 38798592;
static const size_t O_L5R   = 39847168;

// ---------------- scratch ----------------
__device__ float    g_convB[16777216];
__device__ float    g_convR[16777216];
__device__ float    g_poolB[4194304];
__device__ float    g_poolR[4194304];
__device__ uint16_t g_pbin[2][16777216];    // channel-last bf16 sign planes (ping-pong)
__device__ uint16_t g_prealH[2][16777216];  // channel-last bf16 hi planes
__device__ uint16_t g_prealL[2][16777216];  // channel-last bf16 lo planes
__device__ uint16_t g_bwb[4571136];         // transposed binary weights [oc][tap][cin]
__device__ uint16_t g_bwrH[4571136];        // transposed real weights hi
__device__ uint16_t g_bwrL[4571136];        // transposed real weights lo
__device__ float    g_mean[1024];
__device__ float    g_rstd[1024];

static const size_t BW1 = 0;         // 128*128*9
static const size_t BW2 = 147456;    // 256*128*9
static const size_t BW3 = 442368;    // 256*256*9
static const size_t BW4 = 1032192;   // 512*256*9
static const size_t BW5 = 2211840;   // 512*512*9

// ---------------- bf16 helpers ----------------
__device__ __forceinline__ uint16_t f2bf(float x) {
    uint16_t r; asm("cvt.rn.bf16.f32 %0, %1;" : "=h"(r) : "f"(x)); return r;
}
__device__ __forceinline__ float bf2f(uint16_t h) {
    return __uint_as_float(((uint32_t)h) << 16);
}

// ---------------- weight prep: binary sign, transposed tap-major, bf16 ----------------
__global__ void wsignT_k(const float* __restrict__ w, uint16_t* __restrict__ bwT, int CIN) {
    int oc = blockIdx.x;
    int tid = threadIdx.x;
    int K = CIN * 9;
    const float* wp = w + (size_t)oc * K;
    double s = 0.0;
    for (int i = tid; i < K; i += 256) s += (double)wp[i];
    __shared__ double sh[256];
    sh[tid] = s; __syncthreads();
    for (int st = 128; st > 0; st >>= 1) {
        if (tid < st) sh[tid] += sh[tid + st];
        __syncthreads();
    }
    float m = (float)(sh[0] / (double)K);
    for (int i = tid; i < K; i += 256) {
        float d = wp[i] - m;
        uint16_t v = (d > 0.f) ? 0x3F80 : ((d < 0.f) ? 0xBF80 : 0);
        int cin = i / 9, tap = i % 9;
        bwT[((size_t)oc * 9 + tap) * CIN + cin] = v;
    }
}

// ---------------- weight prep: real hi/lo bf16 (separate arrays), transposed ----------------
__global__ void wrealT_k(const float* __restrict__ w, uint16_t* __restrict__ wH,
                         uint16_t* __restrict__ wL, int CIN) {
    size_t i = (size_t)blockIdx.x * 256 + threadIdx.x;
    int tap = (int)(i % 9);
    size_t t = i / 9;
    int cin = (int)(t % CIN);
    int oc  = (int)(t / CIN);
    float x = w[i];
    uint16_t hi = f2bf(x);
    float lo = x - bf2f(hi);
    size_t a = ((size_t)oc * 9 + tap) * CIN + cin;
    wH[a] = hi;
    wL[a] = f2bf(lo);
}

// ---------------- FUSED: conv0 (FFMA, Cin=3) + wsignT(w1) ----------------
// blocks [0,4096): conv0 tiles; blocks [4096,4224): wsign rows for w1 (CIN=128).
__global__ void __launch_bounds__(256) conv0wsign_k(const float* __restrict__ x,
                                                    const float* __restrict__ w0,
                                                    float* __restrict__ out,
                                                    const float* __restrict__ w1,
                                                    uint16_t* __restrict__ bwT) {
    __shared__ float As[9][64];
    __shared__ float Bs[10][10];
    __shared__ double shd[256];
    int tid = threadIdx.x;

    if (blockIdx.x >= 4096) {
        // ---- wsignT for w1, CIN=128 ----
        int oc = blockIdx.x - 4096;
        const int CIN = 128, K = 128 * 9;
        const float* wp = w1 + (size_t)oc * K;
        double s = 0.0;
        for (int i = tid; i < K; i += 256) s += (double)wp[i];
        shd[tid] = s; __syncthreads();
        for (int st = 128; st > 0; st >>= 1) {
            if (tid < st) shd[tid] += shd[tid + st];
            __syncthreads();
        }
        float m = (float)(shd[0] / (double)K);
        for (int i = tid; i < K; i += 256) {
            float d = wp[i] - m;
            uint16_t v = (d > 0.f) ? 0x3F80 : ((d < 0.f) ? 0xBF80 : 0);
            int cin = i / 9, tap = i % 9;
            bwT[((size_t)oc * 9 + tap) * CIN + cin] = v;
        }
        return;
    }

    // ---- conv0: CIN=3, H=32, Cout=128 ----
    const int CIN = 3, HH = 32, Cout = 128;
    int bx = blockIdx.x;
    int tile = bx & 15;
    int ty0 = (tile / 4) * 8;
    int tx0 = (tile % 4) * 8;
    int oc0 = ((bx >> 4) & 1) * 64;
    int n   = bx >> 5;
    int pos_t = tid & 15;
    int oc_t  = tid >> 4;

    float acc[4][4];
#pragma unroll
    for (int j = 0; j < 4; j++)
#pragma unroll
        for (int i = 0; i < 4; i++) acc[j][i] = 0.f;

    const float* inN = x + (size_t)n * CIN * HH * HH;

    for (int cin = 0; cin < CIN; cin++) {
        for (int idx = tid; idx < 576; idx += 256) {
            int oc = idx / 9, tap = idx % 9;
            As[tap][oc] = w0[(((size_t)(oc0 + oc)) * CIN + cin) * 9 + tap];
        }
        if (tid < 100) {
            int r = tid / 10, c = tid % 10;
            int gy = ty0 + r - 1, gx = tx0 + c - 1;
            float v = 0.f;
            if (gy >= 0 && gy < HH && gx >= 0 && gx < HH)
                v = inN[(size_t)cin * HH * HH + gy * HH + gx];
            Bs[r][c] = v;
        }
        __syncthreads();
#pragma unroll
        for (int tap = 0; tap < 9; tap++) {
            int dy = tap / 3, dx = tap % 3;
            float4 wv = *(const float4*)&As[tap][oc_t * 4];
#pragma unroll
            for (int j = 0; j < 4; j++) {
                int p = pos_t + 16 * j;
                float bv = Bs[(p >> 3) + dy][(p & 7) + dx];
                acc[j][0] += bv * wv.x;
                acc[j][1] += bv * wv.y;
                acc[j][2] += bv * wv.z;
                acc[j][3] += bv * wv.w;
            }
        }
        __syncthreads();
    }

#pragma unroll
    for (int j = 0; j < 4; j++) {
        int p = pos_t + 16 * j;
        int oy = ty0 + (p >> 3), ox = tx0 + (p & 7);
#pragma unroll
        for (int i = 0; i < 4; i++) {
            int oc = oc0 + oc_t * 4 + i;
            out[(((size_t)n * Cout + oc) * HH + oy) * HH + ox] = acc[j][i];
        }
    }
}

// ---------------- bf16 MMA ----------------
__device__ __forceinline__ void mma_bf16(float* d, const uint32_t* a, const uint32_t* b) {
    asm volatile(
        "mma.sync.aligned.m16n8k16.row.col.f32.bf16.bf16.f32 "
        "{%0,%1,%2,%3}, {%4,%5,%6,%7}, {%8,%9}, {%0,%1,%2,%3};\n"
        : "+f"(d[0]), "+f"(d[1]), "+f"(d[2]), "+f"(d[3])
        : "r"(a[0]), "r"(a[1]), "r"(a[2]), "r"(a[3]),
          "r"(b[0]), "r"(b[1]));
}

// ---------------- implicit-GEMM conv v4: prepacked planes, tap-major K, hi/lo split arrays ----------------
// Block: 128 threads, 4 warps. Tile M=128 (oc) x N=64 (positions); warp tile 32x64.
// K order = tap*CIN + cin; chunks of 16 lie within one tap (CIN%16==0).
// Staging = pure LDG.128 -> STS (no per-element math; hi/lo planes are separate u16 arrays,
// so loaded words are already kpair-packed; zero PRMT).
template<int CIN, int H, bool SPLIT, bool POOL>
__global__ void __launch_bounds__(128) convmma_k(const uint16_t* __restrict__ inH,
                                                 const uint16_t* __restrict__ inL,
                                                 const uint16_t* __restrict__ wH,
                                                 const uint16_t* __restrict__ wL,
                                                 float* __restrict__ out,
                                                 int Cout) {
    constexpr int Wd = H;
    constexpr int HW = H * H;
    constexpr int K  = CIN * 9;
    constexpr int NCH = K / 16;
    constexpr int LGHW = (HW == 1024) ? 10 : (HW == 256) ? 8 : 6;
    constexpr int LGW  = (H == 32) ? 5 : (H == 16) ? 4 : 3;
    constexpr int NS = SPLIT ? 2 : 1;

    __shared__ uint32_t As[2][NS][8][136];
    __shared__ uint32_t Bs[2][NS][8][72];

    int tid  = threadIdx.x;
    int lane = tid & 31;
    int warp = tid >> 5;
    int gid  = lane >> 2;
    int tig  = lane & 3;

    int col0 = blockIdx.x * 64;
    int oc0  = blockIdx.y * 128;

    int bc  = tid & 63;
    int bkh = tid >> 6;
    int gcol = col0 + bc;
    int n   = gcol >> LGHW;
    int pos = gcol & (HW - 1);
    int y   = pos >> LGW;
    int x   = pos & (Wd - 1);

    const uint16_t* awH = wH + (size_t)(oc0 + tid) * K;
    const uint16_t* awL = SPLIT ? (wL + (size_t)(oc0 + tid) * K) : nullptr;

    // tap state
    int cin0 = 0, dy = -1, dx = -1;
    bool valid;
    size_t rowoff;
    {
        int iy = y + dy, ix = x + dx;
        valid = (iy >= 0 && iy < H && ix >= 0 && ix < Wd);
        rowoff = ((size_t)n * HW + (size_t)(iy * Wd + ix)) * CIN;
    }

    float acc[2][8][4];
#pragma unroll
    for (int mt = 0; mt < 2; mt++)
#pragma unroll
        for (int nt = 0; nt < 8; nt++)
#pragma unroll
            for (int r = 0; r < 4; r++) acc[mt][nt][r] = 0.f;

    uint4 vaH[2], vaL[2], vbH, vbL;
    const uint4 z4 = make_uint4(0, 0, 0, 0);

    auto load_chunk = [&](int c) {
        int k0 = c * 16;
        vaH[0] = *(const uint4*)(awH + k0);
        vaH[1] = *(const uint4*)(awH + k0 + 8);
        vbH = valid ? *(const uint4*)(inH + rowoff + cin0 + bkh * 8) : z4;
        if (SPLIT) {
            vaL[0] = *(const uint4*)(awL + k0);
            vaL[1] = *(const uint4*)(awL + k0 + 8);
            vbL = valid ? *(const uint4*)(inL + rowoff + cin0 + bkh * 8) : z4;
        }
        cin0 += 16;
        if (cin0 == CIN) {
            cin0 = 0;
            dx++;
            if (dx > 1) { dx = -1; dy++; }
            int iy = y + dy, ix = x + dx;
            valid = (iy >= 0 && iy < H && ix >= 0 && ix < Wd);
            rowoff = ((size_t)n * HW + (size_t)(iy * Wd + ix)) * CIN;
        }
    };

    auto sts_chunk = [&](int b) {
        As[b][0][0][tid] = vaH[0].x; As[b][0][1][tid] = vaH[0].y;
        As[b][0][2][tid] = vaH[0].z; As[b][0][3][tid] = vaH[0].w;
        As[b][0][4][tid] = vaH[1].x; As[b][0][5][tid] = vaH[1].y;
        As[b][0][6][tid] = vaH[1].z; As[b][0][7][tid] = vaH[1].w;
        Bs[b][0][bkh * 4 + 0][bc] = vbH.x;
        Bs[b][0][bkh * 4 + 1][bc] = vbH.y;
        Bs[b][0][bkh * 4 + 2][bc] = vbH.z;
        Bs[b][0][bkh * 4 + 3][bc] = vbH.w;
        if (SPLIT) {
            As[b][1][0][tid] = vaL[0].x; As[b][1][1][tid] = vaL[0].y;
            As[b][1][2][tid] = vaL[0].z; As[b][1][3][tid] = vaL[0].w;
            As[b][1][4][tid] = vaL[1].x; As[b][1][5][tid] = vaL[1].y;
            As[b][1][6][tid] = vaL[1].z; As[b][1][7][tid] = vaL[1].w;
            Bs[b][1][bkh * 4 + 0][bc] = vbL.x;
            Bs[b][1][bkh * 4 + 1][bc] = vbL.y;
            Bs[b][1][bkh * 4 + 2][bc] = vbL.z;
            Bs[b][1][bkh * 4 + 3][bc] = vbL.w;
        }
    };

    // prologue
    load_chunk(0);
    sts_chunk(0);
    __syncthreads();

    for (int c = 0; c < NCH; c++) {
        int cur = c & 1;
        bool more = (c + 1 < NCH);
        if (more) load_chunk(c + 1);

        uint32_t af[NS][2][4], bf[NS][8][2];
#pragma unroll
        for (int s = 0; s < NS; s++) {
#pragma unroll
            for (int mt = 0; mt < 2; mt++) {
                int m0 = warp * 32 + mt * 16 + gid;
                af[s][mt][0] = As[cur][s][tig][m0];
                af[s][mt][1] = As[cur][s][tig][m0 + 8];
                af[s][mt][2] = As[cur][s][tig + 4][m0];
                af[s][mt][3] = As[cur][s][tig + 4][m0 + 8];
            }
#pragma unroll
            for (int nt = 0; nt < 8; nt++) {
                bf[s][nt][0] = Bs[cur][s][tig][nt * 8 + gid];
                bf[s][nt][1] = Bs[cur][s][tig + 4][nt * 8 + gid];
            }
        }
#pragma unroll
        for (int mt = 0; mt < 2; mt++)
#pragma unroll
            for (int nt = 0; nt < 8; nt++) {
                if (SPLIT) {
                    mma_bf16(acc[mt][nt], af[1][mt], bf[0][nt]);
                    mma_bf16(acc[mt][nt], af[0][mt], bf[1][nt]);
                }
                mma_bf16(acc[mt][nt], af[0][mt], bf[0][nt]);
            }

        if (more) sts_chunk(cur ^ 1);
        __syncthreads();
    }

    // ---- epilogue ----
    if (!POOL) {
#pragma unroll
        for (int mt = 0; mt < 2; mt++) {
#pragma unroll
            for (int nt = 0; nt < 8; nt++) {
                int cc = col0 + nt * 8 + 2 * tig;
                int n_ = cc >> LGHW;
                int pp = cc & (HW - 1);
#pragma unroll
                for (int h = 0; h < 2; h++) {
                    int m = oc0 + warp * 32 + mt * 16 + gid + 8 * h;
                    float2 v = make_float2(acc[mt][nt][2 * h], acc[mt][nt][2 * h + 1]);
                    *(float2*)&out[((size_t)n_ * Cout + m) * HW + pp] = v;
                }
            }
        }
    } else {
        constexpr int PST = H / 8;
        constexpr int HO = H / 2;
#pragma unroll
        for (int mt = 0; mt < 2; mt++) {
#pragma unroll
            for (int nt = 0; nt < 8; nt++) {
                if (((nt / PST) & 1) != 0) continue;
                int np = nt + PST;
                int cc = col0 + nt * 8 + 2 * tig;
                int n_ = cc >> LGHW;
                int pos_ = cc & (HW - 1);
                int oy = (pos_ >> LGW) >> 1;
                int ox = (pos_ & (Wd - 1)) >> 1;
#pragma unroll
                for (int h = 0; h < 2; h++) {
                    int m = oc0 + warp * 32 + mt * 16 + gid + 8 * h;
                    float v = fmaxf(fmaxf(acc[mt][nt][2 * h], acc[mt][nt][2 * h + 1]),
                                    fmaxf(acc[mt][np][2 * h], acc[mt][np][2 * h + 1]));
                    out[((size_t)n_ * Cout + m) * (HO * HO) + oy * HO + ox] = v;
                }
            }
        }
    }
}

// ---------------- BN stats ----------------
__global__ void bnstats_k(const float* __restrict__ x, int C, int HW,
                          float* __restrict__ mean, float* __restrict__ rstd) {
    int c = blockIdx.x;
    int tid = threadIdx.x;
    double s1 = 0.0, s2 = 0.0;
    for (int n = 0; n < NB; n++) {
        const float* xp = x + ((size_t)n * C + c) * HW;
        for (int p = tid; p < HW; p += 256) {
            float v = xp[p];
            s1 += (double)v;
            s2 += (double)v * (double)v;
        }
    }
    __shared__ double sh1[256], sh2[256];
    sh1[tid] = s1; sh2[tid] = s2; __syncthreads();
    for (int st = 128; st > 0; st >>= 1) {
        if (tid < st) { sh1[tid] += sh1[tid + st]; sh2[tid] += sh2[tid + st]; }
        __syncthreads();
    }
    if (tid == 0) {
        double M = (double)NB * HW;
        double m = sh1[0] / M;
        double var = sh2[0] / M - m * m;
        mean[c] = (float)m;
        rstd[c] = (float)(1.0 / sqrt(var + 1e-5));
    }
}

// ---------------- BN apply + hardtanh + channel-last plane pack (hi/lo split) ----------------
template<bool BIN, bool REALP, bool WF32>
__global__ void bnht_pack_k(const float* __restrict__ x, float* __restrict__ y32,
                            uint16_t* __restrict__ pbin,
                            uint16_t* __restrict__ pH, uint16_t* __restrict__ pL,
                            const float* __restrict__ mean, const float* __restrict__ rstd,
                            const float* __restrict__ g, const float* __restrict__ bb,
                            int C, int HW) {
    __shared__ float ts[32][33];
    int tx = threadIdx.x & 31, ty = threadIdx.x >> 5;
    int p0 = blockIdx.x * 32, c0 = blockIdx.y * 32, n = blockIdx.z;
#pragma unroll
    for (int r = 0; r < 4; r++) {
        int c = c0 + ty + r * 8;
        size_t idx = ((size_t)n * C + c) * HW + p0 + tx;
        float v = x[idx];
        v = (v - mean[c]) * rstd[c] * g[c] + bb[c];
        v = fminf(1.f, fmaxf(-1.f, v));
        if (WF32) y32[idx] = v;
        ts[ty + r * 8][tx] = v;
    }
    __syncthreads();
#pragma unroll
    for (int r = 0; r < 4; r++) {
        int p = p0 + ty + r * 8;
        int c = c0 + tx;
        float v = ts[tx][ty + r * 8];
        size_t a = ((size_t)n * HW + p) * C + c;
        if (BIN)
            pbin[a] = (v > 0.f) ? 0x3F80 : ((v < 0.f) ? 0xBF80 : 0);
        if (REALP) {
            uint16_t hi = f2bf(v);
            float lo = v - bf2f(hi);
            pH[a] = hi;
            pL[a] = f2bf(lo);
        }
    }
}

// ---------------- plain BN apply + hardtanh (L5 outputs) ----------------
__global__ void bnht_k(const float* __restrict__ x, float* __restrict__ y,
                       const float* __restrict__ mean, const float* __restrict__ rstd,
                       const float* __restrict__ g, const float* __restrict__ bb,
                       int lgHW, int Cmask) {
    size_t i = (size_t)blockIdx.x * 256 + threadIdx.x;
    int c = (int)((i >> lgHW) & (size_t)Cmask);
    float v = (x[i] - mean[c]) * rstd[c] * g[c] + bb[c];
    y[i] = fminf(1.f, fmaxf(-1.f, v));
}

// ---------------- copy ----------------
__global__ void copy_k(const float* __restrict__ src, float* __restrict__ dst) {
    size_t i = (size_t)blockIdx.x * 256 + threadIdx.x;
    dst[i] = src[i];
}

// ---------------- FC ----------------
__global__ void fc_k(const float* __restrict__ p, const float* __restrict__ w,
                     const float* __restrict__ b, float* __restrict__ out) {
    int n = blockIdx.x;
    int tid = threadIdx.x;
    float acc[10];
#pragma unroll
    for (int j = 0; j < 10; j++) acc[j] = 0.f;
    const float* pn = p + (size_t)n * 8192;
    for (int k = tid; k < 8192; k += 256) {
        float pv = pn[k];
#pragma unroll
        for (int j = 0; j < 10; j++) acc[j] += pv * w[(size_t)j * 8192 + k];
    }
    __shared__ float sh[256];
    for (int j = 0; j < 10; j++) {
        sh[tid] = acc[j]; __syncthreads();
        for (int st = 128; st > 0; st >>= 1) {
            if (tid < st) sh[tid] += sh[tid + st];
            __syncthreads();
        }
        if (tid == 0) out[n * 10 + j] = sh[0] + b[j];
        __syncthreads();
    }
}

// ---------------- host launch ----------------
extern "C" void kernel_launch(void* const* d_in, const int* in_sizes, int n_in,
                              void* d_out, int out_size) {
    (void)in_sizes; (void)n_in; (void)out_size;
    const float* x   = (const float*)d_in[0];
    const float* w0  = (const float*)d_in[1];
    const float* w1  = (const float*)d_in[2];
    const float* w2  = (const float*)d_in[3];
    const float* w3  = (const float*)d_in[4];
    const float* w4  = (const float*)d_in[5];
    const float* w5  = (const float*)d_in[6];
    const float* fcw = (const float*)d_in[7];
    const float* fcb = (const float*)d_in[8];
    const float* G[6], *B[6];
    for (int i = 0; i < 6; i++) { G[i] = (const float*)d_in[9 + 2*i]; B[i] = (const float*)d_in[10 + 2*i]; }
    float* out = (float*)d_out;

    float *convB, *convR, *poolB, *poolR, *mean, *rstd;
    uint16_t *pbin, *prH, *prL, *bwb, *bwrH, *bwrL;
    cudaGetSymbolAddress((void**)&convB, g_convB);
    cudaGetSymbolAddress((void**)&convR, g_convR);
    cudaGetSymbolAddress((void**)&poolB, g_poolB);
    cudaGetSymbolAddress((void**)&poolR, g_poolR);
    cudaGetSymbolAddress((void**)&pbin,  g_pbin);
    cudaGetSymbolAddress((void**)&prH,   g_prealH);
    cudaGetSymbolAddress((void**)&prL,   g_prealL);
    cudaGetSymbolAddress((void**)&bwb,   g_bwb);
    cudaGetSymbolAddress((void**)&bwrH,  g_bwrH);
    cudaGetSymbolAddress((void**)&bwrL,  g_bwrL);
    cudaGetSymbolAddress((void**)&mean,  g_mean);
    cudaGetSymbolAddress((void**)&rstd,  g_rstd);
    uint16_t* pb[2]  = { pbin, pbin + 16777216 };
    uint16_t* pH[2]  = { prH,  prH  + 16777216 };
    uint16_t* pL[2]  = { prL,  prL  + 16777216 };

    // launch order arranged so ncu profiles index 3 = convmma L1 binary
    conv0wsign_k<<<4224, 256>>>(x, w0, convB, w1, bwb + BW1);                        // 0
    bnstats_k<<<128, 256>>>(convB, 128, 1024, mean, rstd);                           // 1
    bnht_pack_k<true, true, false><<<dim3(32, 4, NB), 256>>>(                        // 2
        convB, nullptr, pb[0], pH[0], pL[0], mean, rstd, G[0], B[0], 128, 1024);

    // Layer 1: 128->128 @32, fused pool -> 16
    convmma_k<128, 32, false, true><<<dim3(2048, 1), 128>>>(                         // 3  <- PROFILED
        pb[0], nullptr, bwb + BW1, nullptr, poolB, 128);
    wrealT_k<<<576, 256>>>(w1, bwrH + BW1, bwrL + BW1, 128);                         // 4
    convmma_k<128, 32, true,  true><<<dim3(2048, 1), 128>>>(                         // 5
        pH[0], pL[0], bwrH + BW1, bwrL + BW1, poolR, 128);
    wsignT_k<<<256, 256>>>(w2, bwb + BW2, 128);
    wrealT_k<<<1152, 256>>>(w2, bwrH + BW2, bwrL + BW2, 128);
    wsignT_k<<<256, 256>>>(w3, bwb + BW3, 256);
    wrealT_k<<<2304, 256>>>(w3, bwrH + BW3, bwrL + BW3, 256);
    wsignT_k<<<512, 256>>>(w4, bwb + BW4, 256);
    wrealT_k<<<4608, 256>>>(w4, bwrH + BW4, bwrL + BW4, 256);
    wsignT_k<<<512, 256>>>(w5, bwb + BW5, 512);
    wrealT_k<<<9216, 256>>>(w5, bwrH + BW5, bwrL + BW5, 512);
    bnstats_k<<<128, 256>>>(poolB, 128, 256, mean, rstd);
    bnht_pack_k<true, false, true><<<dim3(8, 4, NB), 256>>>(
        poolB, out + O_L1B, pb[1], nullptr, nullptr, mean, rstd, G[1], B[1], 128, 256);
    bnstats_k<<<128, 256>>>(poolR, 128, 256, mean + 512, rstd + 512);
    bnht_pack_k<false, true, true><<<dim3(8, 4, NB), 256>>>(
        poolR, out + O_L1R, nullptr, pH[1], pL[1], mean + 512, rstd + 512, G[1], B[1], 128, 256);

    // Layer 2: 128->256 @16, no pool
    convmma_k<128, 16, false, false><<<dim3(512, 2), 128>>>(
        pb[1], nullptr, bwb + BW2, nullptr, convB, 256);
    convmma_k<128, 16, true,  false><<<dim3(512, 2), 128>>>(
        pH[1], pL[1], bwrH + BW2, bwrL + BW2, convR, 256);
    bnstats_k<<<256, 256>>>(convB, 256, 256, mean, rstd);
    bnht_pack_k<true, false, true><<<dim3(8, 8, NB), 256>>>(
        convB, out + O_L2B, pb[0], nullptr, nullptr, mean, rstd, G[2], B[2], 256, 256);
    bnstats_k<<<256, 256>>>(convR, 256, 256, mean + 512, rstd + 512);
    bnht_pack_k<false, true, true><<<dim3(8, 8, NB), 256>>>(
        convR, out + O_L2R, nullptr, pH[0], pL[0], mean + 512, rstd + 512, G[2], B[2], 256, 256);

    // Layer 3: 256->256 @16, fused pool -> 8
    convmma_k<256, 16, false, true><<<dim3(512, 2), 128>>>(
        pb[0], nullptr, bwb + BW3, nullptr, poolB, 256);
    convmma_k<256, 16, true,  true><<<dim3(512, 2), 128>>>(
        pH[0], pL[0], bwrH + BW3, bwrL + BW3, poolR, 256);
    bnstats_k<<<256, 256>>>(poolB, 256, 64, mean, rstd);
    bnht_pack_k<true, false, true><<<dim3(2, 8, NB), 256>>>(
        poolB, out + O_L3B, pb[1], nullptr, nullptr, mean, rstd, G[3], B[3], 256, 64);
    bnstats_k<<<256, 256>>>(poolR, 256, 64, mean + 512, rstd + 512);
    bnht_pack_k<false, true, true><<<dim3(2, 8, NB), 256>>>(
        poolR, out + O_L3R, nullptr, pH[1], pL[1], mean + 512, rstd + 512, G[3], B[3], 256, 64);

    // Layer 4: 256->512 @8, no pool
    convmma_k<256, 8, false, false><<<dim3(128, 4), 128>>>(
        pb[1], nullptr, bwb + BW4, nullptr, convB, 512);
    convmma_k<256, 8, true,  false><<<dim3(128, 4), 128>>>(
        pH[1], pL[1], bwrH + BW4, bwrL + BW4, convR, 512);
    bnstats_k<<<512, 256>>>(convB, 512, 64, mean, rstd);
    bnht_pack_k<true, false, true><<<dim3(2, 16, NB), 256>>>(
        convB, out + O_L4B, pb[0], nullptr, nullptr, mean, rstd, G[4], B[4], 512, 64);
    bnstats_k<<<512, 256>>>(convR, 512, 64, mean + 512, rstd + 512);
    bnht_pack_k<false, true, true><<<dim3(2, 16, NB), 256>>>(
        convR, out + O_L4R, nullptr, pH[0], pL[0], mean + 512, rstd + 512, G[4], B[4], 512, 64);

    // Layer 5: 512->512 @8, fused pool -> 4
    convmma_k<512, 8, false, true><<<dim3(128, 4), 128>>>(
        pb[0], nullptr, bwb + BW5, nullptr, poolB, 512);
    convmma_k<512, 8, true,  true><<<dim3(128, 4), 128>>>(
        pH[0], pL[0], bwrH + BW5, bwrL + BW5, poolR, 512);
    bnstats_k<<<512, 256>>>(poolB, 512, 16, mean, rstd);
    bnht_k<<<(NB * 512 * 16) / 256, 256>>>(poolB, out + O_L5B, mean, rstd, G[5], B[5], 4, 511);
    bnstats_k<<<512, 256>>>(poolR, 512, 16, mean + 512, rstd + 512);
    bnht_k<<<(NB * 512 * 16) / 256, 256>>>(poolR, out + O_L5R, mean + 512, rstd + 512, G[5], B[5], 4, 511);

    // penul + FC
    copy_k<<<(NB * 8192) / 256, 256>>>(out + O_L5B, out + O_PENUL);
    fc_k<<<NB, 256>>>(out + O_PENUL, fcw, fcb, out + O_OUT);
}

// round 11
// speedup vs baseline: 1.7506x; 1.4285x over previous
#include <cuda_runtime.h>
#include <cstddef>
#include <cstdint>

#define NB 128  // batch

// ---------------- output layout (tuple concat, fp32) ----------------
static const size_t O_OUT   = 0;
static const size_t O_PENUL = 1280;
static const size_t O_L1B   = 1049856;
static const size_t O_L1R   = 5244160;
static const size_t O_L2B   = 9438464;
static const size_t O_L2R   = 17827072;
static const size_t O_L3B   = 26215680;
static const size_t O_L3R   = 28312832;
static const size_t O_L4B   = 30409984;
static const size_t O_L4R   = 34604288;
static const size_t O_L5B   = 38798592;
static const size_t O_L5R   = 39847168;

// ---------------- scratch ----------------
__device__ float    g_convB[16777216];
__device__ float    g_convR[16777216];
__device__ float    g_poolB[4194304];
__device__ float    g_poolR[4194304];
__device__ uint16_t g_pbin[2][16777216];    // channel-last bf16 sign planes
__device__ uint16_t g_prealH[2][16777216];  // channel-last bf16 hi planes
__device__ uint16_t g_prealL[2][16777216];  // channel-last bf16 lo planes
__device__ uint16_t g_bwb[4571136];         // tap-major binary weights (staging)
__device__ uint16_t g_bwrH[4571136];        // tap-major real hi (staging)
__device__ uint16_t g_bwrL[4571136];        // tap-major real lo (staging)
__device__ uint4    g_bwfB[571392];         // FRAGMENT-packed binary weights
__device__ uint4    g_bwfH[571392];         // FRAGMENT-packed real hi
__device__ uint4    g_bwfL[571392];         // FRAGMENT-packed real lo
__device__ float    g_mean[1024];
__device__ float    g_rstd[1024];

static const size_t BW1 = 0;         // elems: 128*128*9
static const size_t BW2 = 147456;
static const size_t BW3 = 442368;
static const size_t BW4 = 1032192;
static const size_t BW5 = 2211840;
static const size_t FW1 = 0;         // fragment entries = elems/8
static const size_t FW2 = 18432;
static const size_t FW3 = 55296;
static const size_t FW4 = 129024;
static const size_t FW5 = 276480;

// ---------------- bf16 helpers ----------------
__device__ __forceinline__ uint16_t f2bf(float x) {
    uint16_t r; asm("cvt.rn.bf16.f32 %0, %1;" : "=h"(r) : "f"(x)); return r;
}
__device__ __forceinline__ float bf2f(uint16_t h) {
    return __uint_as_float(((uint32_t)h) << 16);
}

// ---------------- weight prep: binary sign, tap-major u16 (staging) ----------------
__global__ void wsignT_k(const float* __restrict__ w, uint16_t* __restrict__ bwT, int CIN) {
    int oc = blockIdx.x;
    int tid = threadIdx.x;
    int K = CIN * 9;
    const float* wp = w + (size_t)oc * K;
    double s = 0.0;
    for (int i = tid; i < K; i += 256) s += (double)wp[i];
    __shared__ double sh[256];
    sh[tid] = s; __syncthreads();
    for (int st = 128; st > 0; st >>= 1) {
        if (tid < st) sh[tid] += sh[tid + st];
        __syncthreads();
    }
    float m = (float)(sh[0] / (double)K);
    for (int i = tid; i < K; i += 256) {
        float d = wp[i] - m;
        uint16_t v = (d > 0.f) ? 0x3F80 : ((d < 0.f) ? 0xBF80 : 0);
        int cin = i / 9, tap = i % 9;
        bwT[((size_t)oc * 9 + tap) * CIN + cin] = v;
    }
}

// ---------------- weight prep: real hi/lo bf16, tap-major (staging) ----------------
__global__ void wrealT_k(const float* __restrict__ w, uint16_t* __restrict__ wH,
                         uint16_t* __restrict__ wL, int CIN) {
    size_t i = (size_t)blockIdx.x * 256 + threadIdx.x;
    int tap = (int)(i % 9);
    size_t t = i / 9;
    int cin = (int)(t % CIN);
    int oc  = (int)(t / CIN);
    float x = w[i];
    uint16_t hi = f2bf(x);
    float lo = x - bf2f(hi);
    size_t a = ((size_t)oc * 9 + tap) * CIN + cin;
    wH[a] = hi;
    wL[a] = f2bf(lo);
}

// ---------------- fragmentize: tap-major u16 [oc][k] -> MMA fragment entries ----------------
// entry i: lane=i&31, mt=(i>>5)&1, warp=(i>>6)&3, rest=i>>8, c=rest%NCH, ocblk=rest/NCH
// m0 = ocblk*128+warp*32+mt*16+gid, k0 = c*16+tig*2
// uint4 = (a0,a1,a2,a3): a0=pack(m0,k0..k0+1) a1=m0+8 a2=k0+8 a3=both
__global__ void wfrag_k(const uint16_t* __restrict__ in, uint4* __restrict__ out, int K) {
    int NCH = K / 16;
    size_t i = (size_t)blockIdx.x * 256 + threadIdx.x;
    int lane = (int)(i & 31);
    int mt   = (int)((i >> 5) & 1);
    int wrp  = (int)((i >> 6) & 3);
    size_t rest = i >> 8;
    int c     = (int)(rest % NCH);
    int ocblk = (int)(rest / NCH);
    int gid = lane >> 2, tig = lane & 3;
    int m0 = ocblk * 128 + wrp * 32 + mt * 16 + gid;
    int k0 = c * 16 + tig * 2;
    const uint16_t* r0 = in + (size_t)m0 * K;
    const uint16_t* r1 = in + (size_t)(m0 + 8) * K;
    uint4 v;
    v.x = (uint32_t)r0[k0]     | ((uint32_t)r0[k0 + 1] << 16);
    v.y = (uint32_t)r1[k0]     | ((uint32_t)r1[k0 + 1] << 16);
    v.z = (uint32_t)r0[k0 + 8] | ((uint32_t)r0[k0 + 9] << 16);
    v.w = (uint32_t)r1[k0 + 8] | ((uint32_t)r1[k0 + 9] << 16);
    out[i] = v;
}

// ---------------- FUSED: conv0 (FFMA, Cin=3) + w1 sign -> FRAGMENTS directly ----------------
// blocks [0,4096): conv0; blocks [4096,4160): w1 fragment writer (64 oc-pair groups).
__global__ void __launch_bounds__(256) conv0wsign_k(const float* __restrict__ x,
                                                    const float* __restrict__ w0,
                                                    float* __restrict__ out,
                                                    const float* __restrict__ w1,
                                                    uint4* __restrict__ wfrag) {
    __shared__ float As[9][64];
    __shared__ float Bs[10][10];
    __shared__ double shd[256];
    int tid = threadIdx.x;

    if (blockIdx.x >= 4096) {
        // group = (warp w, mt, gid): rows oc_lo = w*32+mt*16+gid and oc_lo+8. K=1152, NCH=72.
        int grp = blockIdx.x - 4096;       // 0..63
        int w_  = grp >> 4;
        int mt  = (grp >> 3) & 1;
        int gid = grp & 7;
        int oc_lo = w_ * 32 + mt * 16 + gid;
        int oc_hi = oc_lo + 8;
        const int K = 1152;
        int half = tid >> 7;               // 0 -> oc_lo, 1 -> oc_hi
        int t    = tid & 127;
        const float* wp = w1 + (size_t)(half ? oc_hi : oc_lo) * K;
        double s = 0.0;
        for (int i = t; i < K; i += 128) s += (double)wp[i];
        shd[tid] = s; __syncthreads();
        for (int st = 64; st > 0; st >>= 1) {
            if (t < st) shd[tid] += shd[tid + st];
            __syncthreads();
        }
        float m_lo = (float)(shd[0]   / (double)K);
        float m_hi = (float)(shd[128] / (double)K);
        const float* wlo = w1 + (size_t)oc_lo * K;
        const float* whi = w1 + (size_t)oc_hi * K;
        auto sgn = [](float v, float m) -> uint32_t {
            float d = v - m;
            return (d > 0.f) ? 0x3F80u : ((d < 0.f) ? 0xBF80u : 0u);
        };
        auto src = [](const float* p, int k) -> float {
            int tap = k >> 7, cin = k & 127;   // k = tap*128+cin
            return p[cin * 9 + tap];
        };
        for (int e = tid; e < 72 * 4; e += 256) {
            int c = e >> 2, tig = e & 3;
            int k0 = c * 16 + tig * 2;
            uint4 v;
            v.x = sgn(src(wlo, k0), m_lo)     | (sgn(src(wlo, k0 + 1), m_lo) << 16);
            v.y = sgn(src(whi, k0), m_hi)     | (sgn(src(whi, k0 + 1), m_hi) << 16);
            v.z = sgn(src(wlo, k0 + 8), m_lo) | (sgn(src(wlo, k0 + 9), m_lo) << 16);
            v.w = sgn(src(whi, k0 + 8), m_hi) | (sgn(src(whi, k0 + 9), m_hi) << 16);
            wfrag[((size_t)c * 4 + w_) * 64 + mt * 32 + gid * 4 + tig] = v;
        }
        return;
    }

    // ---- conv0: CIN=3, H=32, Cout=128 ----
    const int CIN = 3, HH = 32, Cout = 128;
    int bx = blockIdx.x;
    int tile = bx & 15;
    int ty0 = (tile / 4) * 8;
    int tx0 = (tile % 4) * 8;
    int oc0 = ((bx >> 4) & 1) * 64;
    int n   = bx >> 5;
    int pos_t = tid & 15;
    int oc_t  = tid >> 4;

    float acc[4][4];
#pragma unroll
    for (int j = 0; j < 4; j++)
#pragma unroll
        for (int i = 0; i < 4; i++) acc[j][i] = 0.f;

    const float* inN = x + (size_t)n * CIN * HH * HH;

    for (int cin = 0; cin < CIN; cin++) {
        for (int idx = tid; idx < 576; idx += 256) {
            int oc = idx / 9, tap = idx % 9;
            As[tap][oc] = w0[(((size_t)(oc0 + oc)) * CIN + cin) * 9 + tap];
        }
        if (tid < 100) {
            int r = tid / 10, c = tid % 10;
            int gy = ty0 + r - 1, gx = tx0 + c - 1;
            float v = 0.f;
            if (gy >= 0 && gy < HH && gx >= 0 && gx < HH)
                v = inN[(size_t)cin * HH * HH + gy * HH + gx];
            Bs[r][c] = v;
        }
        __syncthreads();
#pragma unroll
        for (int tap = 0; tap < 9; tap++) {
            int dy = tap / 3, dx = tap % 3;
            float4 wv = *(const float4*)&As[tap][oc_t * 4];
#pragma unroll
            for (int j = 0; j < 4; j++) {
                int p = pos_t + 16 * j;
                float bv = Bs[(p >> 3) + dy][(p & 7) + dx];
                acc[j][0] += bv * wv.x;
                acc[j][1] += bv * wv.y;
                acc[j][2] += bv * wv.z;
                acc[j][3] += bv * wv.w;
            }
        }
        __syncthreads();
    }

#pragma unroll
    for (int j = 0; j < 4; j++) {
        int p = pos_t + 16 * j;
        int oy = ty0 + (p >> 3), ox = tx0 + (p & 7);
#pragma unroll
        for (int i = 0; i < 4; i++) {
            int oc = oc0 + oc_t * 4 + i;
            out[(((size_t)n * Cout + oc) * HH + oy) * HH + ox] = acc[j][i];
        }
    }
}

// ---------------- bf16 MMA ----------------
__device__ __forceinline__ void mma_bf16(float* d, const uint32_t* a, const uint32_t* b) {
    asm volatile(
        "mma.sync.aligned.m16n8k16.row.col.f32.bf16.bf16.f32 "
        "{%0,%1,%2,%3}, {%4,%5,%6,%7}, {%8,%9}, {%0,%1,%2,%3};\n"
        : "+f"(d[0]), "+f"(d[1]), "+f"(d[2]), "+f"(d[3])
        : "r"(a[0]), "r"(a[1]), "r"(a[2]), "r"(a[3]),
          "r"(b[0]), "r"(b[1]));
}

// ---------------- implicit-GEMM conv v5: A fragments direct from global ----------------
// Block: 128 threads, 4 warps. Tile M=128 x N=64; warp tile 32x64.
// A: fragment-packed weights -> one LDG.128 per (chunk, mt) per lane; NO smem for A.
// B: channel-last planes -> STS -> fragment LDS (double-buffered, 1 sync/chunk).
template<int CIN, int H, bool SPLIT, bool POOL>
__global__ void __launch_bounds__(128) convmma_k(const uint16_t* __restrict__ inH,
                                                 const uint16_t* __restrict__ inL,
                                                 const uint4* __restrict__ wfH,
                                                 const uint4* __restrict__ wfL,
                                                 float* __restrict__ out,
                                                 int Cout) {
    constexpr int Wd = H;
    constexpr int HW = H * H;
    constexpr int K  = CIN * 9;
    constexpr int NCH = K / 16;
    constexpr int LGHW = (HW == 1024) ? 10 : (HW == 256) ? 8 : 6;
    constexpr int LGW  = (H == 32) ? 5 : (H == 16) ? 4 : 3;
    constexpr int NS = SPLIT ? 2 : 1;

    __shared__ uint32_t Bs[2][NS][8][72];

    int tid  = threadIdx.x;
    int lane = tid & 31;
    int warp = tid >> 5;
    int gid  = lane >> 2;
    int tig  = lane & 3;

    int col0 = blockIdx.x * 64;
    int oc0  = blockIdx.y * 128;

    int bc  = tid & 63;
    int bkh = tid >> 6;
    int gcol = col0 + bc;
    int n   = gcol >> LGHW;
    int pos = gcol & (HW - 1);
    int y   = pos >> LGW;
    int x   = pos & (Wd - 1);

    // A fragment base: entries per ocblk = NCH*256; per chunk: c*256 + warp*64 + mt*32 + lane
    size_t abase = (size_t)(oc0 >> 7) * NCH * 256 + (size_t)warp * 64 + lane;

    // tap state for B
    int cin0 = 0, dy = -1, dx = -1;
    bool valid;
    size_t rowoff;
    {
        int iy = y + dy, ix = x + dx;
        valid = (iy >= 0 && iy < H && ix >= 0 && ix < Wd);
        rowoff = ((size_t)n * HW + (size_t)(iy * Wd + ix)) * CIN;
    }

    float acc[2][8][4];
#pragma unroll
    for (int mt = 0; mt < 2; mt++)
#pragma unroll
        for (int nt = 0; nt < 8; nt++)
#pragma unroll
            for (int r = 0; r < 4; r++) acc[mt][nt][r] = 0.f;

    uint4 acurH[2], acurL[2], anxtH[2], anxtL[2], vbH, vbL;
    const uint4 z4 = make_uint4(0, 0, 0, 0);

    auto load_A = [&](int c, uint4* aH, uint4* aL) {
#pragma unroll
        for (int mt = 0; mt < 2; mt++) {
            aH[mt] = wfH[abase + (size_t)c * 256 + mt * 32];
            if (SPLIT) aL[mt] = wfL[abase + (size_t)c * 256 + mt * 32];
        }
    };
    auto load_B = [&]() {
        vbH = valid ? *(const uint4*)(inH + rowoff + cin0 + bkh * 8) : z4;
        if (SPLIT) vbL = valid ? *(const uint4*)(inL + rowoff + cin0 + bkh * 8) : z4;
        cin0 += 16;
        if (cin0 == CIN) {
            cin0 = 0;
            dx++;
            if (dx > 1) { dx = -1; dy++; }
            int iy = y + dy, ix = x + dx;
            valid = (iy >= 0 && iy < H && ix >= 0 && ix < Wd);
            rowoff = ((size_t)n * HW + (size_t)(iy * Wd + ix)) * CIN;
        }
    };
    auto sts_B = [&](int b) {
        Bs[b][0][bkh * 4 + 0][bc] = vbH.x;
        Bs[b][0][bkh * 4 + 1][bc] = vbH.y;
        Bs[b][0][bkh * 4 + 2][bc] = vbH.z;
        Bs[b][0][bkh * 4 + 3][bc] = vbH.w;
        if (SPLIT) {
            Bs[b][1][bkh * 4 + 0][bc] = vbL.x;
            Bs[b][1][bkh * 4 + 1][bc] = vbL.y;
            Bs[b][1][bkh * 4 + 2][bc] = vbL.z;
            Bs[b][1][bkh * 4 + 3][bc] = vbL.w;
        }
    };

    // prologue
    load_A(0, acurH, acurL);
    load_B();
    sts_B(0);
    __syncthreads();

    for (int c = 0; c < NCH; c++) {
        int cur = c & 1;
        bool more = (c + 1 < NCH);
        if (more) {
            load_B();                       // LDGs for next B
            load_A(c + 1, anxtH, anxtL);    // LDGs for next A fragments
        }

        uint32_t bf[NS][8][2];
#pragma unroll
        for (int s = 0; s < NS; s++)
#pragma unroll
            for (int nt = 0; nt < 8; nt++) {
                bf[s][nt][0] = Bs[cur][s][tig][nt * 8 + gid];
                bf[s][nt][1] = Bs[cur][s][tig + 4][nt * 8 + gid];
            }
#pragma unroll
        for (int mt = 0; mt < 2; mt++)
#pragma unroll
            for (int nt = 0; nt < 8; nt++) {
                if (SPLIT) {
                    mma_bf16(acc[mt][nt], (const uint32_t*)&acurL[mt], bf[0][nt]);
                    mma_bf16(acc[mt][nt], (const uint32_t*)&acurH[mt], bf[1][nt]);
                }
                mma_bf16(acc[mt][nt], (const uint32_t*)&acurH[mt], bf[0][nt]);
            }

        if (more) {
            sts_B(cur ^ 1);
            acurH[0] = anxtH[0]; acurH[1] = anxtH[1];
            if (SPLIT) { acurL[0] = anxtL[0]; acurL[1] = anxtL[1]; }
        }
        __syncthreads();
    }

    // ---- epilogue ----
    if (!POOL) {
#pragma unroll
        for (int mt = 0; mt < 2; mt++) {
#pragma unroll
            for (int nt = 0; nt < 8; nt++) {
                int cc = col0 + nt * 8 + 2 * tig;
                int n_ = cc >> LGHW;
                int pp = cc & (HW - 1);
#pragma unroll
                for (int h = 0; h < 2; h++) {
                    int m = oc0 + warp * 32 + mt * 16 + gid + 8 * h;
                    float2 v = make_float2(acc[mt][nt][2 * h], acc[mt][nt][2 * h + 1]);
                    *(float2*)&out[((size_t)n_ * Cout + m) * HW + pp] = v;
                }
            }
        }
    } else {
        constexpr int PST = H / 8;
        constexpr int HO = H / 2;
#pragma unroll
        for (int mt = 0; mt < 2; mt++) {
#pragma unroll
            for (int nt = 0; nt < 8; nt++) {
                if (((nt / PST) & 1) != 0) continue;
                int np = nt + PST;
                int cc = col0 + nt * 8 + 2 * tig;
                int n_ = cc >> LGHW;
                int pos_ = cc & (HW - 1);
                int oy = (pos_ >> LGW) >> 1;
                int ox = (pos_ & (Wd - 1)) >> 1;
#pragma unroll
                for (int h = 0; h < 2; h++) {
                    int m = oc0 + warp * 32 + mt * 16 + gid + 8 * h;
                    float v = fmaxf(fmaxf(acc[mt][nt][2 * h], acc[mt][nt][2 * h + 1]),
                                    fmaxf(acc[mt][np][2 * h], acc[mt][np][2 * h + 1]));
                    out[((size_t)n_ * Cout + m) * (HO * HO) + oy * HO + ox] = v;
                }
            }
        }
    }
}

// ---------------- BN stats ----------------
__global__ void bnstats_k(const float* __restrict__ x, int C, int HW,
                          float* __restrict__ mean, float* __restrict__ rstd) {
    int c = blockIdx.x;
    int tid = threadIdx.x;
    double s1 = 0.0, s2 = 0.0;
    for (int n = 0; n < NB; n++) {
        const float* xp = x + ((size_t)n * C + c) * HW;
        for (int p = tid; p < HW; p += 256) {
            float v = xp[p];
            s1 += (double)v;
            s2 += (double)v * (double)v;
        }
    }
    __shared__ double sh1[256], sh2[256];
    sh1[tid] = s1; sh2[tid] = s2; __syncthreads();
    for (int st = 128; st > 0; st >>= 1) {
        if (tid < st) { sh1[tid] += sh1[tid + st]; sh2[tid] += sh2[tid + st]; }
        __syncthreads();
    }
    if (tid == 0) {
        double M = (double)NB * HW;
        double m = sh1[0] / M;
        double var = sh2[0] / M - m * m;
        mean[c] = (float)m;
        rstd[c] = (float)(1.0 / sqrt(var + 1e-5));
    }
}

// ---------------- BN apply + hardtanh + channel-last plane pack ----------------
template<bool BIN, bool REALP, bool WF32>
__global__ void bnht_pack_k(const float* __restrict__ x, float* __restrict__ y32,
                            uint16_t* __restrict__ pbin,
                            uint16_t* __restrict__ pH, uint16_t* __restrict__ pL,
                            const float* __restrict__ mean, const float* __restrict__ rstd,
                            const float* __restrict__ g, const float* __restrict__ bb,
                            int C, int HW) {
    __shared__ float ts[32][33];
    int tx = threadIdx.x & 31, ty = threadIdx.x >> 5;
    int p0 = blockIdx.x * 32, c0 = blockIdx.y * 32, n = blockIdx.z;
#pragma unroll
    for (int r = 0; r < 4; r++) {
        int c = c0 + ty + r * 8;
        size_t idx = ((size_t)n * C + c) * HW + p0 + tx;
        float v = x[idx];
        v = (v - mean[c]) * rstd[c] * g[c] + bb[c];
        v = fminf(1.f, fmaxf(-1.f, v));
        if (WF32) y32[idx] = v;
        ts[ty + r * 8][tx] = v;
    }
    __syncthreads();
#pragma unroll
    for (int r = 0; r < 4; r++) {
        int p = p0 + ty + r * 8;
        int c = c0 + tx;
        float v = ts[tx][ty + r * 8];
        size_t a = ((size_t)n * HW + p) * C + c;
        if (BIN)
            pbin[a] = (v > 0.f) ? 0x3F80 : ((v < 0.f) ? 0xBF80 : 0);
        if (REALP) {
            uint16_t hi = f2bf(v);
            float lo = v - bf2f(hi);
            pH[a] = hi;
            pL[a] = f2bf(lo);
        }
    }
}

// ---------------- plain BN apply + hardtanh (L5 outputs) ----------------
__global__ void bnht_k(const float* __restrict__ x, float* __restrict__ y,
                       const float* __restrict__ mean, const float* __restrict__ rstd,
                       const float* __restrict__ g, const float* __restrict__ bb,
                       int lgHW, int Cmask) {
    size_t i = (size_t)blockIdx.x * 256 + threadIdx.x;
    int c = (int)((i >> lgHW) & (size_t)Cmask);
    float v = (x[i] - mean[c]) * rstd[c] * g[c] + bb[c];
    y[i] = fminf(1.f, fmaxf(-1.f, v));
}

// ---------------- copy ----------------
__global__ void copy_k(const float* __restrict__ src, float* __restrict__ dst) {
    size_t i = (size_t)blockIdx.x * 256 + threadIdx.x;
    dst[i] = src[i];
}

// ---------------- FC ----------------
__global__ void fc_k(const float* __restrict__ p, const float* __restrict__ w,
                     const float* __restrict__ b, float* __restrict__ out) {
    int n = blockIdx.x;
    int tid = threadIdx.x;
    float acc[10];
#pragma unroll
    for (int j = 0; j < 10; j++) acc[j] = 0.f;
    const float* pn = p + (size_t)n * 8192;
    for (int k = tid; k < 8192; k += 256) {
        float pv = pn[k];
#pragma unroll
        for (int j = 0; j < 10; j++) acc[j] += pv * w[(size_t)j * 8192 + k];
    }
    __shared__ float sh[256];
    for (int j = 0; j < 10; j++) {
        sh[tid] = acc[j]; __syncthreads();
        for (int st = 128; st > 0; st >>= 1) {
            if (tid < st) sh[tid] += sh[tid + st];
            __syncthreads();
        }
        if (tid == 0) out[n * 10 + j] = sh[0] + b[j];
        __syncthreads();
    }
}

// ---------------- host launch ----------------
extern "C" void kernel_launch(void* const* d_in, const int* in_sizes, int n_in,
                              void* d_out, int out_size) {
    (void)in_sizes; (void)n_in; (void)out_size;
    const float* x   = (const float*)d_in[0];
    const float* w0  = (const float*)d_in[1];
    const float* w1  = (const float*)d_in[2];
    const float* w2  = (const float*)d_in[3];
    const float* w3  = (const float*)d_in[4];
    const float* w4  = (const float*)d_in[5];
    const float* w5  = (const float*)d_in[6];
    const float* fcw = (const float*)d_in[7];
    const float* fcb = (const float*)d_in[8];
    const float* G[6], *B[6];
    for (int i = 0; i < 6; i++) { G[i] = (const float*)d_in[9 + 2*i]; B[i] = (const float*)d_in[10 + 2*i]; }
    float* out = (float*)d_out;

    float *convB, *poolB, *poolR, *mean, *rstd;
    uint16_t *pbin, *prH, *prL, *bwb, *bwrH, *bwrL;
    uint4 *bwfB, *bwfH, *bwfL;
    cudaGetSymbolAddress((void**)&convB, g_convB);
    float* convR; cudaGetSymbolAddress((void**)&convR, g_convR);
    cudaGetSymbolAddress((void**)&poolB, g_poolB);
    cudaGetSymbolAddress((void**)&poolR, g_poolR);
    cudaGetSymbolAddress((void**)&pbin,  g_pbin);
    cudaGetSymbolAddress((void**)&prH,   g_prealH);
    cudaGetSymbolAddress((void**)&prL,   g_prealL);
    cudaGetSymbolAddress((void**)&bwb,   g_bwb);
    cudaGetSymbolAddress((void**)&bwrH,  g_bwrH);
    cudaGetSymbolAddress((void**)&bwrL,  g_bwrL);
    cudaGetSymbolAddress((void**)&bwfB,  g_bwfB);
    cudaGetSymbolAddress((void**)&bwfH,  g_bwfH);
    cudaGetSymbolAddress((void**)&bwfL,  g_bwfL);
    cudaGetSymbolAddress((void**)&mean,  g_mean);
    cudaGetSymbolAddress((void**)&rstd,  g_rstd);
    uint16_t* pb[2]  = { pbin, pbin + 16777216 };
    uint16_t* pH[2]  = { prH,  prH  + 16777216 };
    uint16_t* pL[2]  = { prL,  prL  + 16777216 };

    // launch order arranged so ncu profiles index 3 = convmma L1 binary
    conv0wsign_k<<<4160, 256>>>(x, w0, convB, w1, bwfB + FW1);                       // 0
    bnstats_k<<<128, 256>>>(convB, 128, 1024, mean, rstd);                           // 1
    bnht_pack_k<true, true, false><<<dim3(32, 4, NB), 256>>>(                        // 2
        convB, nullptr, pb[0], pH[0], pL[0], mean, rstd, G[0], B[0], 128, 1024);

    // Layer 1: 128->128 @32, fused pool -> 16
    convmma_k<128, 32, false, true><<<dim3(2048, 1), 128>>>(                         // 3 <- PROFILED
        pb[0], nullptr, bwfB + FW1, nullptr, poolB, 128);
    wrealT_k<<<576, 256>>>(w1, bwrH + BW1, bwrL + BW1, 128);
    wfrag_k<<<72, 256>>>(bwrH + BW1, bwfH + FW1, 1152);
    wfrag_k<<<72, 256>>>(bwrL + BW1, bwfL + FW1, 1152);
    convmma_k<128, 32, true, true><<<dim3(2048, 1), 128>>>(
        pH[0], pL[0], bwfH + FW1, bwfL + FW1, poolR, 128);

    // weight prep for layers 2..5
    wsignT_k<<<256, 256>>>(w2, bwb + BW2, 128);
    wfrag_k<<<144, 256>>>(bwb + BW2, bwfB + FW2, 1152);
    wrealT_k<<<1152, 256>>>(w2, bwrH + BW2, bwrL + BW2, 128);
    wfrag_k<<<144, 256>>>(bwrH + BW2, bwfH + FW2, 1152);
    wfrag_k<<<144, 256>>>(bwrL + BW2, bwfL + FW2, 1152);
    wsignT_k<<<256, 256>>>(w3, bwb + BW3, 256);
    wfrag_k<<<288, 256>>>(bwb + BW3, bwfB + FW3, 2304);
    wrealT_k<<<2304, 256>>>(w3, bwrH + BW3, bwrL + BW3, 256);
    wfrag_k<<<288, 256>>>(bwrH + BW3, bwfH + FW3, 2304);
    wfrag_k<<<288, 256>>>(bwrL + BW3, bwfL + FW3, 2304);
    wsignT_k<<<512, 256>>>(w4, bwb + BW4, 256);
    wfrag_k<<<576, 256>>>(bwb + BW4, bwfB + FW4, 2304);
    wrealT_k<<<4608, 256>>>(w4, bwrH + BW4, bwrL + BW4, 256);
    wfrag_k<<<576, 256>>>(bwrH + BW4, bwfH + FW4, 2304);
    wfrag_k<<<576, 256>>>(bwrL + BW4, bwfL + FW4, 2304);
    wsignT_k<<<512, 256>>>(w5, bwb + BW5, 512);
    wfrag_k<<<1152, 256>>>(bwb + BW5, bwfB + FW5, 4608);
    wrealT_k<<<9216, 256>>>(w5, bwrH + BW5, bwrL + BW5, 512);
    wfrag_k<<<1152, 256>>>(bwrH + BW5, bwfH + FW5, 4608);
    wfrag_k<<<1152, 256>>>(bwrL + BW5, bwfL + FW5, 4608);

    bnstats_k<<<128, 256>>>(poolB, 128, 256, mean, rstd);
    bnht_pack_k<true, false, true><<<dim3(8, 4, NB), 256>>>(
        poolB, out + O_L1B, pb[1], nullptr, nullptr, mean, rstd, G[1], B[1], 128, 256);
    bnstats_k<<<128, 256>>>(poolR, 128, 256, mean + 512, rstd + 512);
    bnht_pack_k<false, true, true><<<dim3(8, 4, NB), 256>>>(
        poolR, out + O_L1R, nullptr, pH[1], pL[1], mean + 512, rstd + 512, G[1], B[1], 128, 256);

    // Layer 2: 128->256 @16, no pool
    convmma_k<128, 16, false, false><<<dim3(512, 2), 128>>>(
        pb[1], nullptr, bwfB + FW2, nullptr, convB, 256);
    convmma_k<128, 16, true, false><<<dim3(512, 2), 128>>>(
        pH[1], pL[1], bwfH + FW2, bwfL + FW2, convR, 256);
    bnstats_k<<<256, 256>>>(convB, 256, 256, mean, rstd);
    bnht_pack_k<true, false, true><<<dim3(8, 8, NB), 256>>>(
        convB, out + O_L2B, pb[0], nullptr, nullptr, mean, rstd, G[2], B[2], 256, 256);
    bnstats_k<<<256, 256>>>(convR, 256, 256, mean + 512, rstd + 512);
    bnht_pack_k<false, true, true><<<dim3(8, 8, NB), 256>>>(
        convR, out + O_L2R, nullptr, pH[0], pL[0], mean + 512, rstd + 512, G[2], B[2], 256, 256);

    // Layer 3: 256->256 @16, fused pool -> 8
    convmma_k<256, 16, false, true><<<dim3(512, 2), 128>>>(
        pb[0], nullptr, bwfB + FW3, nullptr, poolB, 256);
    convmma_k<256, 16, true, true><<<dim3(512, 2), 128>>>(
        pH[0], pL[0], bwfH + FW3, bwfL + FW3, poolR, 256);
    bnstats_k<<<256, 256>>>(poolB, 256, 64, mean, rstd);
    bnht_pack_k<true, false, true><<<dim3(2, 8, NB), 256>>>(
        poolB, out + O_L3B, pb[1], nullptr, nullptr, mean, rstd, G[3], B[3], 256, 64);
    bnstats_k<<<256, 256>>>(poolR, 256, 64, mean + 512, rstd + 512);
    bnht_pack_k<false, true, true><<<dim3(2, 8, NB), 256>>>(
        poolR, out + O_L3R, nullptr, pH[1], pL[1], mean + 512, rstd + 512, G[3], B[3], 256, 64);

    // Layer 4: 256->512 @8, no pool
    convmma_k<256, 8, false, false><<<dim3(128, 4), 128>>>(
        pb[1], nullptr, bwfB + FW4, nullptr, convB, 512);
    convmma_k<256, 8, true, false><<<dim3(128, 4), 128>>>(
        pH[1], pL[1], bwfH + FW4, bwfL + FW4, convR, 512);
    bnstats_k<<<512, 256>>>(convB, 512, 64, mean, rstd);
    bnht_pack_k<true, false, true><<<dim3(2, 16, NB), 256>>>(
        convB, out + O_L4B, pb[0], nullptr, nullptr, mean, rstd, G[4], B[4], 512, 64);
    bnstats_k<<<512, 256>>>(convR, 512, 64, mean + 512, rstd + 512);
    bnht_pack_k<false, true, true><<<dim3(2, 16, NB), 256>>>(
        convR, out + O_L4R, nullptr, pH[0], pL[0], mean + 512, rstd + 512, G[4], B[4], 512, 64);

    // Layer 5: 512->512 @8, fused pool -> 4
    convmma_k<512, 8, false, true><<<dim3(128, 4), 128>>>(
        pb[0], nullptr, bwfB + FW5, nullptr, poolB, 512);
    convmma_k<512, 8, true, true><<<dim3(128, 4), 128>>>(
        pH[0], pL[0], bwfH + FW5, bwfL + FW5, poolR, 512);
    bnstats_k<<<512, 256>>>(poolB, 512, 16, mean, rstd);
    bnht_k<<<(NB * 512 * 16) / 256, 256>>>(poolB, out + O_L5B, mean, rstd, G[5], B[5], 4, 511);
    bnstats_k<<<512, 256>>>(poolR, 512, 16, mean + 512, rstd + 512);
    bnht_k<<<(NB * 512 * 16) / 256, 256>>>(poolR, out + O_L5R, mean + 512, rstd + 512, G[5], B[5], 4, 511);

    // penul + FC
    copy_k<<<(NB * 8192) / 256, 256>>>(out + O_L5B, out + O_PENUL);
    fc_k<<<NB, 256>>>(out + O_PENUL, fcw, fcb, out + O_OUT);
}

// round 12
// speedup vs baseline: 1.7926x; 1.0240x over previous
#include <cuda_runtime.h>
#include <cstddef>
#include <cstdint>

#define NB 128  // batch

// ---------------- output layout (tuple concat, fp32) ----------------
static const size_t O_OUT   = 0;
static const size_t O_PENUL = 1280;
static const size_t O_L1B   = 1049856;
static const size_t O_L1R   = 5244160;
static const size_t O_L2B   = 9438464;
static const size_t O_L2R   = 17827072;
static const size_t O_L3B   = 26215680;
static const size_t O_L3R   = 28312832;
static const size_t O_L4B   = 30409984;
static const size_t O_L4R   = 34604288;
static const size_t O_L5B   = 38798592;
static const size_t O_L5R   = 39847168;

// ---------------- scratch ----------------
__device__ float    g_convB[16777216];
__device__ float    g_convR[16777216];
__device__ float    g_poolB[4194304];
__device__ float    g_poolR[4194304];
__device__ uint16_t g_pbin[2][16777216];
__device__ uint16_t g_prealH[2][16777216];
__device__ uint16_t g_prealL[2][16777216];
__device__ uint16_t g_bwb[4571136];
__device__ uint16_t g_bwrH[4571136];
__device__ uint16_t g_bwrL[4571136];
__device__ uint4    g_bwfB[571392];
__device__ uint4    g_bwfH[571392];
__device__ uint4    g_bwfL[571392];
__device__ float    g_mean[1024];
__device__ float    g_rstd[1024];

static const size_t BW1 = 0;
static const size_t BW2 = 147456;
static const size_t BW3 = 442368;
static const size_t BW4 = 1032192;
static const size_t BW5 = 2211840;
static const size_t FW1 = 0;
static const size_t FW2 = 18432;
static const size_t FW3 = 55296;
static const size_t FW4 = 129024;
static const size_t FW5 = 276480;

// ---------------- bf16 helpers ----------------
__device__ __forceinline__ uint16_t f2bf(float x) {
    uint16_t r; asm("cvt.rn.bf16.f32 %0, %1;" : "=h"(r) : "f"(x)); return r;
}
__device__ __forceinline__ float bf2f(uint16_t h) {
    return __uint_as_float(((uint32_t)h) << 16);
}

// ---------------- weight prep: binary sign, tap-major u16 ----------------
__global__ void wsignT_k(const float* __restrict__ w, uint16_t* __restrict__ bwT, int CIN) {
    int oc = blockIdx.x;
    int tid = threadIdx.x;
    int K = CIN * 9;
    const float* wp = w + (size_t)oc * K;
    double s = 0.0;
    for (int i = tid; i < K; i += 256) s += (double)wp[i];
    __shared__ double sh[256];
    sh[tid] = s; __syncthreads();
    for (int st = 128; st > 0; st >>= 1) {
        if (tid < st) sh[tid] += sh[tid + st];
        __syncthreads();
    }
    float m = (float)(sh[0] / (double)K);
    for (int i = tid; i < K; i += 256) {
        float d = wp[i] - m;
        uint16_t v = (d > 0.f) ? 0x3F80 : ((d < 0.f) ? 0xBF80 : 0);
        int cin = i / 9, tap = i % 9;
        bwT[((size_t)oc * 9 + tap) * CIN + cin] = v;
    }
}

// ---------------- weight prep: real hi/lo bf16, tap-major ----------------
__global__ void wrealT_k(const float* __restrict__ w, uint16_t* __restrict__ wH,
                         uint16_t* __restrict__ wL, int CIN) {
    size_t i = (size_t)blockIdx.x * 256 + threadIdx.x;
    int tap = (int)(i % 9);
    size_t t = i / 9;
    int cin = (int)(t % CIN);
    int oc  = (int)(t / CIN);
    float x = w[i];
    uint16_t hi = f2bf(x);
    float lo = x - bf2f(hi);
    size_t a = ((size_t)oc * 9 + tap) * CIN + cin;
    wH[a] = hi;
    wL[a] = f2bf(lo);
}

// ---------------- fragmentize weights ----------------
__global__ void wfrag_k(const uint16_t* __restrict__ in, uint4* __restrict__ out, int K) {
    int NCH = K / 16;
    size_t i = (size_t)blockIdx.x * 256 + threadIdx.x;
    int lane = (int)(i & 31);
    int mt   = (int)((i >> 5) & 1);
    int wrp  = (int)((i >> 6) & 3);
    size_t rest = i >> 8;
    int c     = (int)(rest % NCH);
    int ocblk = (int)(rest / NCH);
    int gid = lane >> 2, tig = lane & 3;
    int m0 = ocblk * 128 + wrp * 32 + mt * 16 + gid;
    int k0 = c * 16 + tig * 2;
    const uint16_t* r0 = in + (size_t)m0 * K;
    const uint16_t* r1 = in + (size_t)(m0 + 8) * K;
    uint4 v;
    v.x = (uint32_t)r0[k0]     | ((uint32_t)r0[k0 + 1] << 16);
    v.y = (uint32_t)r1[k0]     | ((uint32_t)r1[k0 + 1] << 16);
    v.z = (uint32_t)r0[k0 + 8] | ((uint32_t)r0[k0 + 9] << 16);
    v.w = (uint32_t)r1[k0 + 8] | ((uint32_t)r1[k0 + 9] << 16);
    out[i] = v;
}

// ---------------- FUSED: conv0 + w1 sign fragments ----------------
__global__ void __launch_bounds__(256) conv0wsign_k(const float* __restrict__ x,
                                                    const float* __restrict__ w0,
                                                    float* __restrict__ out,
                                                    const float* __restrict__ w1,
                                                    uint4* __restrict__ wfrag) {
    __shared__ float As[9][64];
    __shared__ float Bs[10][10];
    __shared__ double shd[256];
    int tid = threadIdx.x;

    if (blockIdx.x >= 4096) {
        int grp = blockIdx.x - 4096;
        int w_  = grp >> 4;
        int mt  = (grp >> 3) & 1;
        int gid = grp & 7;
        int oc_lo = w_ * 32 + mt * 16 + gid;
        int oc_hi = oc_lo + 8;
        const int K = 1152;
        int half = tid >> 7;
        int t    = tid & 127;
        const float* wp = w1 + (size_t)(half ? oc_hi : oc_lo) * K;
        double s = 0.0;
        for (int i = t; i < K; i += 128) s += (double)wp[i];
        shd[tid] = s; __syncthreads();
        for (int st = 64; st > 0; st >>= 1) {
            if (t < st) shd[tid] += shd[tid + st];
            __syncthreads();
        }
        float m_lo = (float)(shd[0]   / (double)K);
        float m_hi = (float)(shd[128] / (double)K);
        const float* wlo = w1 + (size_t)oc_lo * K;
        const float* whi = w1 + (size_t)oc_hi * K;
        auto sgn = [](float v, float m) -> uint32_t {
            float d = v - m;
            return (d > 0.f) ? 0x3F80u : ((d < 0.f) ? 0xBF80u : 0u);
        };
        auto src = [](const float* p, int k) -> float {
            int tap = k >> 7, cin = k & 127;
            return p[cin * 9 + tap];
        };
        for (int e = tid; e < 72 * 4; e += 256) {
            int c = e >> 2, tig = e & 3;
            int k0 = c * 16 + tig * 2;
            uint4 v;
            v.x = sgn(src(wlo, k0), m_lo)     | (sgn(src(wlo, k0 + 1), m_lo) << 16);
            v.y = sgn(src(whi, k0), m_hi)     | (sgn(src(whi, k0 + 1), m_hi) << 16);
            v.z = sgn(src(wlo, k0 + 8), m_lo) | (sgn(src(wlo, k0 + 9), m_lo) << 16);
            v.w = sgn(src(whi, k0 + 8), m_hi) | (sgn(src(whi, k0 + 9), m_hi) << 16);
            wfrag[((size_t)c * 4 + w_) * 64 + mt * 32 + gid * 4 + tig] = v;
        }
        return;
    }

    const int CIN = 3, HH = 32, Cout = 128;
    int bx = blockIdx.x;
    int tile = bx & 15;
    int ty0 = (tile / 4) * 8;
    int tx0 = (tile % 4) * 8;
    int oc0 = ((bx >> 4) & 1) * 64;
    int n   = bx >> 5;
    int pos_t = tid & 15;
    int oc_t  = tid >> 4;

    float acc[4][4];
#pragma unroll
    for (int j = 0; j < 4; j++)
#pragma unroll
        for (int i = 0; i < 4; i++) acc[j][i] = 0.f;

    const float* inN = x + (size_t)n * CIN * HH * HH;

    for (int cin = 0; cin < CIN; cin++) {
        for (int idx = tid; idx < 576; idx += 256) {
            int oc = idx / 9, tap = idx % 9;
            As[tap][oc] = w0[(((size_t)(oc0 + oc)) * CIN + cin) * 9 + tap];
        }
        if (tid < 100) {
            int r = tid / 10, c = tid % 10;
            int gy = ty0 + r - 1, gx = tx0 + c - 1;
            float v = 0.f;
            if (gy >= 0 && gy < HH && gx >= 0 && gx < HH)
                v = inN[(size_t)cin * HH * HH + gy * HH + gx];
            Bs[r][c] = v;
        }
        __syncthreads();
#pragma unroll
        for (int tap = 0; tap < 9; tap++) {
            int dy = tap / 3, dx = tap % 3;
            float4 wv = *(const float4*)&As[tap][oc_t * 4];
#pragma unroll
            for (int j = 0; j < 4; j++) {
                int p = pos_t + 16 * j;
                float bv = Bs[(p >> 3) + dy][(p & 7) + dx];
                acc[j][0] += bv * wv.x;
                acc[j][1] += bv * wv.y;
                acc[j][2] += bv * wv.z;
                acc[j][3] += bv * wv.w;
            }
        }
        __syncthreads();
    }

#pragma unroll
    for (int j = 0; j < 4; j++) {
        int p = pos_t + 16 * j;
        int oy = ty0 + (p >> 3), ox = tx0 + (p & 7);
#pragma unroll
        for (int i = 0; i < 4; i++) {
            int oc = oc0 + oc_t * 4 + i;
            out[(((size_t)n * Cout + oc) * HH + oy) * HH + ox] = acc[j][i];
        }
    }
}

// ---------------- bf16 MMA + ldmatrix ----------------
__device__ __forceinline__ void mma_bf16(float* d, const uint32_t* a, const uint32_t* b) {
    asm volatile(
        "mma.sync.aligned.m16n8k16.row.col.f32.bf16.bf16.f32 "
        "{%0,%1,%2,%3}, {%4,%5,%6,%7}, {%8,%9}, {%0,%1,%2,%3};\n"
        : "+f"(d[0]), "+f"(d[1]), "+f"(d[2]), "+f"(d[3])
        : "r"(a[0]), "r"(a[1]), "r"(a[2]), "r"(a[3]),
          "r"(b[0]), "r"(b[1]));
}
__device__ __forceinline__ void ldsm_x4(uint32_t& r0, uint32_t& r1, uint32_t& r2, uint32_t& r3,
                                        uint32_t addr) {
    asm volatile("ldmatrix.sync.aligned.m8n8.x4.shared.b16 {%0,%1,%2,%3}, [%4];"
                 : "=r"(r0), "=r"(r1), "=r"(r2), "=r"(r3) : "r"(addr));
}

// ---------------- implicit-GEMM conv v6: A frags from global, B via ldmatrix ----------------
// Block: 128 threads, 4 warps. Tile M=128 x N=64; warp tile 32x64.
// B smem layout: [n(64)][k(16)] u16, row stride 24 u16 (48B; 8x8 tile rows hit 8 distinct
// 16B bank-slots). Staging: 1 LDG.128 + 1 STS.128 per thread per plane.
// Fragment load: 4 ldmatrix.x4 per warp per plane (lane groups -> (ntE kLo, ntE kHi, ntO kLo, ntO kHi)).
template<int CIN, int H, bool SPLIT, bool POOL>
__global__ void __launch_bounds__(128) convmma_k(const uint16_t* __restrict__ inH,
                                                 const uint16_t* __restrict__ inL,
                                                 const uint4* __restrict__ wfH,
                                                 const uint4* __restrict__ wfL,
                                                 float* __restrict__ out,
                                                 int Cout) {
    constexpr int Wd = H;
    constexpr int HW = H * H;
    constexpr int K  = CIN * 9;
    constexpr int NCH = K / 16;
    constexpr int LGHW = (HW == 1024) ? 10 : (HW == 256) ? 8 : 6;
    constexpr int LGW  = (H == 32) ? 5 : (H == 16) ? 4 : 3;
    constexpr int NS = SPLIT ? 2 : 1;

    __shared__ __align__(16) uint16_t Bs[2][NS][64 * 24];  // 48B row stride

    int tid  = threadIdx.x;
    int lane = tid & 31;
    int warp = tid >> 5;
    int gid  = lane >> 2;
    int tig  = lane & 3;

    int col0 = blockIdx.x * 64;
    int oc0  = blockIdx.y * 128;

    int bc  = tid & 63;
    int bkh = tid >> 6;
    int gcol = col0 + bc;
    int n   = gcol >> LGHW;
    int pos = gcol & (HW - 1);
    int y   = pos >> LGW;
    int x   = pos & (Wd - 1);

    size_t abase = (size_t)(oc0 >> 7) * NCH * 256 + (size_t)warp * 64 + lane;

    // tap state for B
    int cin0 = 0, dy = -1, dx = -1;
    bool valid;
    size_t rowoff;
    {
        int iy = y + dy, ix = x + dx;
        valid = (iy >= 0 && iy < H && ix >= 0 && ix < Wd);
        rowoff = ((size_t)n * HW + (size_t)(iy * Wd + ix)) * CIN;
    }

    float acc[2][8][4];
#pragma unroll
    for (int mt = 0; mt < 2; mt++)
#pragma unroll
        for (int nt = 0; nt < 8; nt++)
#pragma unroll
            for (int r = 0; r < 4; r++) acc[mt][nt][r] = 0.f;

    uint4 acurH[2], acurL[2], anxtH[2], anxtL[2], vbH, vbL;
    const uint4 z4 = make_uint4(0, 0, 0, 0);

    // ldmatrix lane offset (bytes): row = (lane>>4)*8 + (lane&7), khalf = (lane>>3)&1
    uint32_t laneoff = ((((lane >> 4) & 1) * 8 + (lane & 7)) * 48) + (((lane >> 3) & 1) * 16);
    uint32_t bsaddr[2][NS];
#pragma unroll
    for (int b = 0; b < 2; b++)
#pragma unroll
        for (int s = 0; s < NS; s++)
            bsaddr[b][s] = (uint32_t)__cvta_generic_to_shared(&Bs[b][s][0]) + laneoff;

    auto load_A = [&](int c, uint4* aH, uint4* aL) {
#pragma unroll
        for (int mt = 0; mt < 2; mt++) {
            aH[mt] = wfH[abase + (size_t)c * 256 + mt * 32];
            if (SPLIT) aL[mt] = wfL[abase + (size_t)c * 256 + mt * 32];
        }
    };
    auto load_B = [&]() {
        vbH = valid ? *(const uint4*)(inH + rowoff + cin0 + bkh * 8) : z4;
        if (SPLIT) vbL = valid ? *(const uint4*)(inL + rowoff + cin0 + bkh * 8) : z4;
        cin0 += 16;
        if (cin0 == CIN) {
            cin0 = 0;
            dx++;
            if (dx > 1) { dx = -1; dy++; }
            int iy = y + dy, ix = x + dx;
            valid = (iy >= 0 && iy < H && ix >= 0 && ix < Wd);
            rowoff = ((size_t)n * HW + (size_t)(iy * Wd + ix)) * CIN;
        }
    };
    auto sts_B = [&](int b) {
        *(uint4*)&Bs[b][0][bc * 24 + bkh * 8] = vbH;
        if (SPLIT) *(uint4*)&Bs[b][1][bc * 24 + bkh * 8] = vbL;
    };

    // prologue
    load_A(0, acurH, acurL);
    load_B();
    sts_B(0);
    __syncthreads();

    for (int c = 0; c < NCH; c++) {
        int cur = c & 1;
        bool more = (c + 1 < NCH);
        if (more) {
            load_B();
            load_A(c + 1, anxtH, anxtL);
        }

        uint32_t bf[NS][8][2];
#pragma unroll
        for (int s = 0; s < NS; s++)
#pragma unroll
            for (int p = 0; p < 4; p++)
                ldsm_x4(bf[s][2 * p][0], bf[s][2 * p][1],
                        bf[s][2 * p + 1][0], bf[s][2 * p + 1][1],
                        bsaddr[cur][s] + p * 768);   // 16 rows * 48B
#pragma unroll
        for (int mt = 0; mt < 2; mt++)
#pragma unroll
            for (int nt = 0; nt < 8; nt++) {
                if (SPLIT) {
                    mma_bf16(acc[mt][nt], (const uint32_t*)&acurL[mt], bf[0][nt]);
                    mma_bf16(acc[mt][nt], (const uint32_t*)&acurH[mt], bf[1][nt]);
                }
                mma_bf16(acc[mt][nt], (const uint32_t*)&acurH[mt], bf[0][nt]);
            }

        if (more) {
            sts_B(cur ^ 1);
            acurH[0] = anxtH[0]; acurH[1] = anxtH[1];
            if (SPLIT) { acurL[0] = anxtL[0]; acurL[1] = anxtL[1]; }
        }
        __syncthreads();
    }

    // ---- epilogue ----
    if (!POOL) {
#pragma unroll
        for (int mt = 0; mt < 2; mt++) {
#pragma unroll
            for (int nt = 0; nt < 8; nt++) {
                int cc = col0 + nt * 8 + 2 * tig;
                int n_ = cc >> LGHW;
                int pp = cc & (HW - 1);
#pragma unroll
                for (int h = 0; h < 2; h++) {
                    int m = oc0 + warp * 32 + mt * 16 + gid + 8 * h;
                    float2 v = make_float2(acc[mt][nt][2 * h], acc[mt][nt][2 * h + 1]);
                    *(float2*)&out[((size_t)n_ * Cout + m) * HW + pp] = v;
                }
            }
        }
    } else {
        constexpr int PST = H / 8;
        constexpr int HO = H / 2;
#pragma unroll
        for (int mt = 0; mt < 2; mt++) {
#pragma unroll
            for (int nt = 0; nt < 8; nt++) {
                if (((nt / PST) & 1) != 0) continue;
                int np = nt + PST;
                int cc = col0 + nt * 8 + 2 * tig;
                int n_ = cc >> LGHW;
                int pos_ = cc & (HW - 1);
                int oy = (pos_ >> LGW) >> 1;
                int ox = (pos_ & (Wd - 1)) >> 1;
#pragma unroll
                for (int h = 0; h < 2; h++) {
                    int m = oc0 + warp * 32 + mt * 16 + gid + 8 * h;
                    float v = fmaxf(fmaxf(acc[mt][nt][2 * h], acc[mt][nt][2 * h + 1]),
                                    fmaxf(acc[mt][np][2 * h], acc[mt][np][2 * h + 1]));
                    out[((size_t)n_ * Cout + m) * (HO * HO) + oy * HO + ox] = v;
                }
            }
        }
    }
}

// ---------------- BN stats ----------------
__global__ void bnstats_k(const float* __restrict__ x, int C, int HW,
                          float* __restrict__ mean, float* __restrict__ rstd) {
    int c = blockIdx.x;
    int tid = threadIdx.x;
    double s1 = 0.0, s2 = 0.0;
    for (int n = 0; n < NB; n++) {
        const float* xp = x + ((size_t)n * C + c) * HW;
        for (int p = tid; p < HW; p += 256) {
            float v = xp[p];
            s1 += (double)v;
            s2 += (double)v * (double)v;
        }
    }
    __shared__ double sh1[256], sh2[256];
    sh1[tid] = s1; sh2[tid] = s2; __syncthreads();
    for (int st = 128; st > 0; st >>= 1) {
        if (tid < st) { sh1[tid] += sh1[tid + st]; sh2[tid] += sh2[tid + st]; }
        __syncthreads();
    }
    if (tid == 0) {
        double M = (double)NB * HW;
        double m = sh1[0] / M;
        double var = sh2[0] / M - m * m;
        mean[c] = (float)m;
        rstd[c] = (float)(1.0 / sqrt(var + 1e-5));
    }
}

// ---------------- BN apply + hardtanh + channel-last plane pack ----------------
template<bool BIN, bool REALP, bool WF32>
__global__ void bnht_pack_k(const float* __restrict__ x, float* __restrict__ y32,
                            uint16_t* __restrict__ pbin,
                            uint16_t* __restrict__ pH, uint16_t* __restrict__ pL,
                            const float* __restrict__ mean, const float* __restrict__ rstd,
                            const float* __restrict__ g, const float* __restrict__ bb,
                            int C, int HW) {
    __shared__ float ts[32][33];
    int tx = threadIdx.x & 31, ty = threadIdx.x >> 5;
    int p0 = blockIdx.x * 32, c0 = blockIdx.y * 32, n = blockIdx.z;
#pragma unroll
    for (int r = 0; r < 4; r++) {
        int c = c0 + ty + r * 8;
        size_t idx = ((size_t)n * C + c) * HW + p0 + tx;
        float v = x[idx];
        v = (v - mean[c]) * rstd[c] * g[c] + bb[c];
        v = fminf(1.f, fmaxf(-1.f, v));
        if (WF32) y32[idx] = v;
        ts[ty + r * 8][tx] = v;
    }
    __syncthreads();
#pragma unroll
    for (int r = 0; r < 4; r++) {
        int p = p0 + ty + r * 8;
        int c = c0 + tx;
        float v = ts[tx][ty + r * 8];
        size_t a = ((size_t)n * HW + p) * C + c;
        if (BIN)
            pbin[a] = (v > 0.f) ? 0x3F80 : ((v < 0.f) ? 0xBF80 : 0);
        if (REALP) {
            uint16_t hi = f2bf(v);
            float lo = v - bf2f(hi);
            pH[a] = hi;
            pL[a] = f2bf(lo);
        }
    }
}

// ---------------- plain BN apply + hardtanh (L5 outputs) ----------------
__global__ void bnht_k(const float* __restrict__ x, float* __restrict__ y,
                       const float* __restrict__ mean, const float* __restrict__ rstd,
                       const float* __restrict__ g, const float* __restrict__ bb,
                       int lgHW, int Cmask) {
    size_t i = (size_t)blockIdx.x * 256 + threadIdx.x;
    int c = (int)((i >> lgHW) & (size_t)Cmask);
    float v = (x[i] - mean[c]) * rstd[c] * g[c] + bb[c];
    y[i] = fminf(1.f, fmaxf(-1.f, v));
}

// ---------------- copy ----------------
__global__ void copy_k(const float* __restrict__ src, float* __restrict__ dst) {
    size_t i = (size_t)blockIdx.x * 256 + threadIdx.x;
    dst[i] = src[i];
}

// ---------------- FC ----------------
__global__ void fc_k(const float* __restrict__ p, const float* __restrict__ w,
                     const float* __restrict__ b, float* __restrict__ out) {
    int n = blockIdx.x;
    int tid = threadIdx.x;
    float acc[10];
#pragma unroll
    for (int j = 0; j < 10; j++) acc[j] = 0.f;
    const float* pn = p + (size_t)n * 8192;
    for (int k = tid; k < 8192; k += 256) {
        float pv = pn[k];
#pragma unroll
        for (int j = 0; j < 10; j++) acc[j] += pv * w[(size_t)j * 8192 + k];
    }
    __shared__ float sh[256];
    for (int j = 0; j < 10; j++) {
        sh[tid] = acc[j]; __syncthreads();
        for (int st = 128; st > 0; st >>= 1) {
            if (tid < st) sh[tid] += sh[tid + st];
            __syncthreads();
        }
        if (tid == 0) out[n * 10 + j] = sh[0] + b[j];
        __syncthreads();
    }
}

// ---------------- host launch ----------------
extern "C" void kernel_launch(void* const* d_in, const int* in_sizes, int n_in,
                              void* d_out, int out_size) {
    (void)in_sizes; (void)n_in; (void)out_size;
    const float* x   = (const float*)d_in[0];
    const float* w0  = (const float*)d_in[1];
    const float* w1  = (const float*)d_in[2];
    const float* w2  = (const float*)d_in[3];
    const float* w3  = (const float*)d_in[4];
    const float* w4  = (const float*)d_in[5];
    const float* w5  = (const float*)d_in[6];
    const float* fcw = (const float*)d_in[7];
    const float* fcb = (const float*)d_in[8];
    const float* G[6], *B[6];
    for (int i = 0; i < 6; i++) { G[i] = (const float*)d_in[9 + 2*i]; B[i] = (const float*)d_in[10 + 2*i]; }
    float* out = (float*)d_out;

    float *convB, *convR, *poolB, *poolR, *mean, *rstd;
    uint16_t *pbin, *prH, *prL, *bwb, *bwrH, *bwrL;
    uint4 *bwfB, *bwfH, *bwfL;
    cudaGetSymbolAddress((void**)&convB, g_convB);
    cudaGetSymbolAddress((void**)&convR, g_convR);
    cudaGetSymbolAddress((void**)&poolB, g_poolB);
    cudaGetSymbolAddress((void**)&poolR, g_poolR);
    cudaGetSymbolAddress((void**)&pbin,  g_pbin);
    cudaGetSymbolAddress((void**)&prH,   g_prealH);
    cudaGetSymbolAddress((void**)&prL,   g_prealL);
    cudaGetSymbolAddress((void**)&bwb,   g_bwb);
    cudaGetSymbolAddress((void**)&bwrH,  g_bwrH);
    cudaGetSymbolAddress((void**)&bwrL,  g_bwrL);
    cudaGetSymbolAddress((void**)&bwfB,  g_bwfB);
    cudaGetSymbolAddress((void**)&bwfH,  g_bwfH);
    cudaGetSymbolAddress((void**)&bwfL,  g_bwfL);
    cudaGetSymbolAddress((void**)&mean,  g_mean);
    cudaGetSymbolAddress((void**)&rstd,  g_rstd);
    uint16_t* pb[2]  = { pbin, pbin + 16777216 };
    uint16_t* pH[2]  = { prH,  prH  + 16777216 };
    uint16_t* pL[2]  = { prL,  prL  + 16777216 };

    // launch order: index 3 = convmma L1 binary (profiled)
    conv0wsign_k<<<4160, 256>>>(x, w0, convB, w1, bwfB + FW1);                       // 0
    bnstats_k<<<128, 256>>>(convB, 128, 1024, mean, rstd);                           // 1
    bnht_pack_k<true, true, false><<<dim3(32, 4, NB), 256>>>(                        // 2
        convB, nullptr, pb[0], pH[0], pL[0], mean, rstd, G[0], B[0], 128, 1024);

    // Layer 1: 128->128 @32, fused pool -> 16
    convmma_k<128, 32, false, true><<<dim3(2048, 1), 128>>>(                         // 3 <- PROFILED
        pb[0], nullptr, bwfB + FW1, nullptr, poolB, 128);
    wrealT_k<<<576, 256>>>(w1, bwrH + BW1, bwrL + BW1, 128);
    wfrag_k<<<72, 256>>>(bwrH + BW1, bwfH + FW1, 1152);
    wfrag_k<<<72, 256>>>(bwrL + BW1, bwfL + FW1, 1152);
    convmma_k<128, 32, true, true><<<dim3(2048, 1), 128>>>(
        pH[0], pL[0], bwfH + FW1, bwfL + FW1, poolR, 128);

    // weight prep for layers 2..5
    wsignT_k<<<256, 256>>>(w2, bwb + BW2, 128);
    wfrag_k<<<144, 256>>>(bwb + BW2, bwfB + FW2, 1152);
    wrealT_k<<<1152, 256>>>(w2, bwrH + BW2, bwrL + BW2, 128);
    wfrag_k<<<144, 256>>>(bwrH + BW2, bwfH + FW2, 1152);
    wfrag_k<<<144, 256>>>(bwrL + BW2, bwfL + FW2, 1152);
    wsignT_k<<<256, 256>>>(w3, bwb + BW3, 256);
    wfrag_k<<<288, 256>>>(bwb + BW3, bwfB + FW3, 2304);
    wrealT_k<<<2304, 256>>>(w3, bwrH + BW3, bwrL + BW3, 256);
    wfrag_k<<<288, 256>>>(bwrH + BW3, bwfH + FW3, 2304);
    wfrag_k<<<288, 256>>>(bwrL + BW3, bwfL + FW3, 2304);
    wsignT_k<<<512, 256>>>(w4, bwb + BW4, 256);
    wfrag_k<<<576, 256>>>(bwb + BW4, bwfB + FW4, 2304);
    wrealT_k<<<4608, 256>>>(w4, bwrH + BW4, bwrL + BW4, 256);
    wfrag_k<<<576, 256>>>(bwrH + BW4, bwfH + FW4, 2304);
    wfrag_k<<<576, 256>>>(bwrL + BW4, bwfL + FW4, 2304);
    wsignT_k<<<512, 256>>>(w5, bwb + BW5, 512);
    wfrag_k<<<1152, 256>>>(bwb + BW5, bwfB + FW5, 4608);
    wrealT_k<<<9216, 256>>>(w5, bwrH + BW5, bwrL + BW5, 512);
    wfrag_k<<<1152, 256>>>(bwrH + BW5, bwfH + FW5, 4608);
    wfrag_k<<<1152, 256>>>(bwrL + BW5, bwfL + FW5, 4608);

    bnstats_k<<<128, 256>>>(poolB, 128, 256, mean, rstd);
    bnht_pack_k<true, false, true><<<dim3(8, 4, NB), 256>>>(
        poolB, out + O_L1B, pb[1], nullptr, nullptr, mean, rstd, G[1], B[1], 128, 256);
    bnstats_k<<<128, 256>>>(poolR, 128, 256, mean + 512, rstd + 512);
    bnht_pack_k<false, true, true><<<dim3(8, 4, NB), 256>>>(
        poolR, out + O_L1R, nullptr, pH[1], pL[1], mean + 512, rstd + 512, G[1], B[1], 128, 256);

    // Layer 2: 128->256 @16, no pool
    convmma_k<128, 16, false, false><<<dim3(512, 2), 128>>>(
        pb[1], nullptr, bwfB + FW2, nullptr, convB, 256);
    convmma_k<128, 16, true, false><<<dim3(512, 2), 128>>>(
        pH[1], pL[1], bwfH + FW2, bwfL + FW2, convR, 256);
    bnstats_k<<<256, 256>>>(convB, 256, 256, mean, rstd);
    bnht_pack_k<true, false, true><<<dim3(8, 8, NB), 256>>>(
        convB, out + O_L2B, pb[0], nullptr, nullptr, mean, rstd, G[2], B[2], 256, 256);
    bnstats_k<<<256, 256>>>(convR, 256, 256, mean + 512, rstd + 512);
    bnht_pack_k<false, true, true><<<dim3(8, 8, NB), 256>>>(
        convR, out + O_L2R, nullptr, pH[0], pL[0], mean + 512, rstd + 512, G[2], B[2], 256, 256);

    // Layer 3: 256->256 @16, fused pool -> 8
    convmma_k<256, 16, false, true><<<dim3(512, 2), 128>>>(
        pb[0], nullptr, bwfB + FW3, nullptr, poolB, 256);
    convmma_k<256, 16, true, true><<<dim3(512, 2), 128>>>(
        pH[0], pL[0], bwfH + FW3, bwfL + FW3, poolR, 256);
    bnstats_k<<<256, 256>>>(poolB, 256, 64, mean, rstd);
    bnht_pack_k<true, false, true><<<dim3(2, 8, NB), 256>>>(
        poolB, out + O_L3B, pb[1], nullptr, nullptr, mean, rstd, G[3], B[3], 256, 64);
    bnstats_k<<<256, 256>>>(poolR, 256, 64, mean + 512, rstd + 512);
    bnht_pack_k<false, true, true><<<dim3(2, 8, NB), 256>>>(
        poolR, out + O_L3R, nullptr, pH[1], pL[1], mean + 512, rstd + 512, G[3], B[3], 256, 64);

    // Layer 4: 256->512 @8, no pool
    convmma_k<256, 8, false, false><<<dim3(128, 4), 128>>>(
        pb[1], nullptr, bwfB + FW4, nullptr, convB, 512);
    convmma_k<256, 8, true, false><<<dim3(128, 4), 128>>>(
        pH[1], pL[1], bwfH + FW4, bwfL + FW4, convR, 512);
    bnstats_k<<<512, 256>>>(convB, 512, 64, mean, rstd);
    bnht_pack_k<true, false, true><<<dim3(2, 16, NB), 256>>>(
        convB, out + O_L4B, pb[0], nullptr, nullptr, mean, rstd, G[4], B[4], 512, 64);
    bnstats_k<<<512, 256>>>(convR, 512, 64, mean + 512, rstd + 512);
    bnht_pack_k<false, true, true><<<dim3(2, 16, NB), 256>>>(
        convR, out + O_L4R, nullptr, pH[0], pL[0], mean + 512, rstd + 512, G[4], B[4], 512, 64);

    // Layer 5: 512->512 @8, fused pool -> 4
    convmma_k<512, 8, false, true><<<dim3(128, 4), 128>>>(
        pb[0], nullptr, bwfB + FW5, nullptr, poolB, 512);
    convmma_k<512, 8, true, true><<<dim3(128, 4), 128>>>(
        pH[0], pL[0], bwfH + FW5, bwfL + FW5, poolR, 512);
    bnstats_k<<<512, 256>>>(poolB, 512, 16, mean, rstd);
    bnht_k<<<(NB * 512 * 16) / 256, 256>>>(poolB, out + O_L5B, mean, rstd, G[5], B[5], 4, 511);
    bnstats_k<<<512, 256>>>(poolR, 512, 16, mean + 512, rstd + 512);
    bnht_k<<<(NB * 512 * 16) / 256, 256>>>(poolR, out + O_L5R, mean + 512, rstd + 512, G[5], B[5], 4, 511);

    // penul + FC
    copy_k<<<(NB * 8192) / 256, 256>>>(out + O_L5B, out + O_PENUL);
    fc_k<<<NB, 256>>>(out + O_PENUL, fcw, fcb, out + O_OUT);
}